// round 1
// baseline (speedup 1.0000x reference)
#include <cuda_runtime.h>
#include <math.h>

// Problem constants
#define BB   64
#define TT   8
#define DD   512
#define SS   512
#define NKVH 4
// SCALE = 512^-0.5
#define QK_SCALE 0.044194173824159216f
#define EPS 1e-6f

// Scratch (device globals — no allocation allowed)
__device__ float g_q[BB * TT * DD];        // RMS-normed Q            [512][512]
__device__ float g_qt[BB * TT * DD];       // q-tilde = q'(1+kw)@Wk_n * SCALE
__device__ float g_sumsq[BB * NKVH * SS];  // ||k_raw(s)||^2 per (b,n,s)
__device__ int   g_mask_mode;              // 0=int32 1=f32 2=byte 3=16bit

// ---------------------------------------------------------------------------
// Mask dtype sniffer: reads the first 8192 x 32-bit words (32KB — valid under
// every candidate layout since the byte-bool buffer is exactly 32768 bytes).
// Deterministic: same input -> same mode.
// ---------------------------------------------------------------------------
__global__ void k_detect_mask(const unsigned int* __restrict__ m) {
    __shared__ int flags[3];
    int tid = threadIdx.x;
    if (tid < 3) flags[tid] = 1;
    __syncthreads();
    int iok = 1, fok = 1, hok = 1;
    for (int i = tid; i < 8192; i += blockDim.x) {
        unsigned w = m[i];
        if (w > 1u) iok = 0;
        float f = __uint_as_float(w);
        if (!(f == 0.0f || f == 1.0f)) fok = 0;
        unsigned lo = w & 0xFFFFu, hi = w >> 16;
        if (!((lo == 0u || lo == 0x3F80u) && (hi == 0u || hi == 0x3F80u))) hok = 0;
    }
    if (!iok) atomicExch(&flags[0], 0);
    if (!fok) atomicExch(&flags[1], 0);
    if (!hok) atomicExch(&flags[2], 0);
    __syncthreads();
    if (tid == 0)
        g_mask_mode = flags[0] ? 0 : (flags[1] ? 1 : (flags[2] ? 3 : 2));
}

__device__ __forceinline__ bool is_masked(const void* m, int idx, int mode) {
    if (mode == 0) return ((const int*)m)[idx] != 0;
    if (mode == 1) return ((const float*)m)[idx] != 0.0f;
    if (mode == 3) return ((const unsigned short*)m)[idx] != 0;
    return ((const unsigned char*)m)[idx] != 0;
}

// ---------------------------------------------------------------------------
// Kernel 1: Q projection + RMSNorm. One block per (b,t) row, 512 threads.
// q[row,e] = rmsnorm( target[row,:] . Wq[e,:] ) * (1 + qw[e])
// ---------------------------------------------------------------------------
__global__ void __launch_bounds__(512) k_qproj(const float* __restrict__ tgt,
                                               const float* __restrict__ Wq,
                                               const float* __restrict__ qw) {
    int row = blockIdx.x;      // b*T + t
    int tid = threadIdx.x;     // e
    __shared__ float sx[DD];
    __shared__ float sred[512];
    sx[tid] = tgt[row * DD + tid];
    __syncthreads();
    const float4* w4 = (const float4*)(Wq + (size_t)tid * DD);
    const float4* x4 = (const float4*)sx;
    float acc = 0.0f;
#pragma unroll 8
    for (int i = 0; i < DD / 4; i++) {
        float4 w = w4[i];
        float4 x = x4[i];
        acc += w.x * x.x + w.y * x.y + w.z * x.z + w.w * x.w;
    }
    sred[tid] = acc * acc;
    __syncthreads();
    for (int off = 256; off > 0; off >>= 1) {
        if (tid < off) sred[tid] += sred[tid + off];
        __syncthreads();
    }
    float inv = rsqrtf(sred[0] * (1.0f / (float)DD) + EPS);
    g_q[row * DD + tid] = acc * inv * (1.0f + qw[tid]);
}

// ---------------------------------------------------------------------------
// Kernel 2: q-tilde. score linearity: q.(k_norm) = ((q*(1+kw)) @ Wk_n) . h * inv_rms
// One block per (b,t) row, 512 threads over d.
// ---------------------------------------------------------------------------
__global__ void __launch_bounds__(512) k_qtilde(const float* __restrict__ Wk,
                                                const float* __restrict__ kw) {
    int row = blockIdx.x;       // b*T + t
    int t = row & 7;
    int n = t >> 1;             // kv head
    int d = threadIdx.x;
    __shared__ float sq[DD];
    sq[d] = g_q[row * DD + d] * (1.0f + kw[d]);
    __syncthreads();
    const float* wb = Wk + (size_t)(n * DD) * DD + d;
    float acc = 0.0f;
#pragma unroll 8
    for (int e = 0; e < DD; e++) acc += sq[e] * wb[(size_t)e * DD];
    g_qt[row * DD + d] = acc * QK_SCALE;
}

// ---------------------------------------------------------------------------
// Kernel 2b: zero the sumsq accumulator
// ---------------------------------------------------------------------------
__global__ void k_zero_sumsq() {
    int i = blockIdx.x * blockDim.x + threadIdx.x;
    if (i < BB * NKVH * SS) g_sumsq[i] = 0.0f;
}

// ---------------------------------------------------------------------------
// Kernel 3 (dominant, 34.4 GMAC): per-row ||hist[b,s,:] @ Wk_n^T||^2.
// Tiled SGEMM 128x128xK512, BK=8, 256 threads, 8x8 register tile; C-tile is
// squared-and-row-reduced instead of stored. 4 col-blocks atomically add
// partial sums per row.
// grid: 4096 = B(64) * NKV(4) * rowblk(4) * colblk(4)
// ---------------------------------------------------------------------------
__global__ void __launch_bounds__(256) k_knorm(const float* __restrict__ hist,
                                               const float* __restrict__ Wk) {
    int bx = blockIdx.x;
    int cb = bx & 3;
    int rb = (bx >> 2) & 3;
    int n  = (bx >> 4) & 3;
    int b  = bx >> 6;
    int s0 = rb * 128;
    int e0 = cb * 128;

    const float* A  = hist + ((size_t)b * SS + s0) * DD;   // [128][512] rows s
    const float* Bm = Wk + ((size_t)(n * DD + e0)) * DD;   // [128][512] rows e

    __shared__ float As[8][128];
    __shared__ float Bs[8][128];
    __shared__ float red[128][16];

    int tid  = threadIdx.x;
    int trow = tid >> 4;        // 0..15 -> rows trow*8..+7
    int tcol = tid & 15;        // 0..15 -> cols tcol*8..+7
    int lr = tid >> 1;          // 0..127 load row
    int lc = (tid & 1) * 4;     // 0 or 4 load col (within BK)

    float acc[8][8];
#pragma unroll
    for (int i = 0; i < 8; i++)
#pragma unroll
        for (int j = 0; j < 8; j++) acc[i][j] = 0.0f;

    for (int k0 = 0; k0 < DD; k0 += 8) {
        float4 av = *(const float4*)(A  + (size_t)lr * DD + k0 + lc);
        float4 bv = *(const float4*)(Bm + (size_t)lr * DD + k0 + lc);
        __syncthreads();
        As[lc + 0][lr] = av.x; As[lc + 1][lr] = av.y;
        As[lc + 2][lr] = av.z; As[lc + 3][lr] = av.w;
        Bs[lc + 0][lr] = bv.x; Bs[lc + 1][lr] = bv.y;
        Bs[lc + 2][lr] = bv.z; Bs[lc + 3][lr] = bv.w;
        __syncthreads();
#pragma unroll
        for (int k = 0; k < 8; k++) {
            float ar[8], br[8];
            *(float4*)&ar[0] = *(const float4*)&As[k][trow * 8];
            *(float4*)&ar[4] = *(const float4*)&As[k][trow * 8 + 4];
            *(float4*)&br[0] = *(const float4*)&Bs[k][tcol * 8];
            *(float4*)&br[4] = *(const float4*)&Bs[k][tcol * 8 + 4];
#pragma unroll
            for (int i = 0; i < 8; i++)
#pragma unroll
                for (int j = 0; j < 8; j++) acc[i][j] += ar[i] * br[j];
        }
    }

    // Row sum-of-squares over this 128-col slab
#pragma unroll
    for (int i = 0; i < 8; i++) {
        float rs = 0.0f;
#pragma unroll
        for (int j = 0; j < 8; j++) rs += acc[i][j] * acc[i][j];
        red[trow * 8 + i][tcol] = rs;
    }
    __syncthreads();
    if (tid < 128) {
        float s = 0.0f;
#pragma unroll
        for (int c = 0; c < 16; c++) s += red[tid][c];
        atomicAdd(&g_sumsq[((size_t)b * NKVH + n) * SS + s0 + tid], s);
    }
}

// ---------------------------------------------------------------------------
// Kernel 4: scores -> softmax -> attn weights out; ctx = attn@hist;
// tokens = ctx @ Wv_n^T. One block per (b,n), 256 threads, G=2 handled together.
// ---------------------------------------------------------------------------
__global__ void __launch_bounds__(256) k_attn(const float* __restrict__ hist,
                                              const void*  __restrict__ mask,
                                              const float* __restrict__ Wv,
                                              float* __restrict__ out) {
    int b = blockIdx.x >> 2;
    int n = blockIdx.x & 3;
    int tid = threadIdx.x;
    int mode = g_mask_mode;

    __shared__ float sA[2][DD];    // q-tilde, later ctx
    __shared__ float ssc[2][SS];   // scores, later attn
    __shared__ float sred[256];

    // load q-tilde for the 2 group-queries
    for (int i = tid; i < 2 * DD; i += 256)
        sA[i >> 9][i & 511] = g_qt[((size_t)(b * TT + n * 2)) * DD + i];
    __syncthreads();

    // scores
    for (int s = tid; s < SS; s += 256) {
        const float4* h4 = (const float4*)(hist + ((size_t)b * SS + s) * DD);
        const float4* a0 = (const float4*)sA[0];
        const float4* a1 = (const float4*)sA[1];
        float acc0 = 0.0f, acc1 = 0.0f;
#pragma unroll 8
        for (int i = 0; i < DD / 4; i++) {
            float4 h = h4[i];
            float4 x = a0[i];
            float4 y = a1[i];
            acc0 += h.x * x.x + h.y * x.y + h.z * x.z + h.w * x.w;
            acc1 += h.x * y.x + h.y * y.y + h.z * y.z + h.w * y.w;
        }
        float inv = rsqrtf(g_sumsq[((size_t)b * NKVH + n) * SS + s] * (1.0f / (float)DD) + EPS);
        bool msk = is_masked(mask, b * SS + s, mode);
        ssc[0][s] = msk ? -INFINITY : acc0 * inv;
        ssc[1][s] = msk ? -INFINITY : acc1 * inv;
    }
    __syncthreads();

    // softmax per group query + write attn weights
    for (int g = 0; g < 2; g++) {
        float m = fmaxf(ssc[g][tid], ssc[g][tid + 256]);
        sred[tid] = m;
        __syncthreads();
        for (int off = 128; off > 0; off >>= 1) {
            if (tid < off) sred[tid] = fmaxf(sred[tid], sred[tid + off]);
            __syncthreads();
        }
        float rowmax = sred[0];
        __syncthreads();
        float e0 = expf(ssc[g][tid] - rowmax);
        float e1 = expf(ssc[g][tid + 256] - rowmax);
        sred[tid] = e0 + e1;
        __syncthreads();
        for (int off = 128; off > 0; off >>= 1) {
            if (tid < off) sred[tid] += sred[tid + off];
            __syncthreads();
        }
        float invsum = 1.0f / sred[0];
        __syncthreads();
        float a0 = e0 * invsum, a1 = e1 * invsum;
        ssc[g][tid] = a0;
        ssc[g][tid + 256] = a1;
        size_t wbase = (size_t)BB * TT * DD + ((size_t)(b * TT + n * 2 + g)) * SS;
        out[wbase + tid] = a0;
        out[wbase + tid + 256] = a1;
        __syncthreads();
    }

    // ctx[g][d] = sum_s attn[g][s] * hist[b,s,d]
    for (int d = tid; d < DD; d += 256) {
        const float* hp = hist + (size_t)b * SS * DD + d;
        float c0 = 0.0f, c1 = 0.0f;
#pragma unroll 4
        for (int s = 0; s < SS; s++) {
            float h = hp[(size_t)s * DD];
            c0 += ssc[0][s] * h;
            c1 += ssc[1][s] * h;
        }
        sA[0][d] = c0;
        sA[1][d] = c1;
    }
    __syncthreads();

    // tokens[g][e] = sum_d ctx[g][d] * Wv[n*D+e, d]
    for (int e = tid; e < DD; e += 256) {
        const float4* w4 = (const float4*)(Wv + ((size_t)(n * DD + e)) * DD);
        const float4* c0 = (const float4*)sA[0];
        const float4* c1 = (const float4*)sA[1];
        float o0 = 0.0f, o1 = 0.0f;
#pragma unroll 8
        for (int i = 0; i < DD / 4; i++) {
            float4 w = w4[i];
            float4 x = c0[i];
            float4 y = c1[i];
            o0 += w.x * x.x + w.y * x.y + w.z * x.z + w.w * x.w;
            o1 += w.x * y.x + w.y * y.y + w.z * y.z + w.w * y.w;
        }
        out[((size_t)(b * TT + n * 2 + 0)) * DD + e] = o0;
        out[((size_t)(b * TT + n * 2 + 1)) * DD + e] = o1;
    }
}

// ---------------------------------------------------------------------------
extern "C" void kernel_launch(void* const* d_in, const int* in_sizes, int n_in,
                              void* d_out, int out_size) {
    (void)in_sizes; (void)n_in; (void)out_size;
    const float* target = (const float*)d_in[0];
    const float* hist   = (const float*)d_in[1];
    const void*  mask   = d_in[2];
    const float* Wq     = (const float*)d_in[3];
    const float* Wk     = (const float*)d_in[4];
    const float* Wv     = (const float*)d_in[5];
    const float* qw     = (const float*)d_in[6];
    const float* kw     = (const float*)d_in[7];
    float* out = (float*)d_out;

    k_detect_mask<<<1, 256>>>((const unsigned int*)mask);
    k_qproj<<<BB * TT, 512>>>(target, Wq, qw);
    k_qtilde<<<BB * TT, 512>>>(Wk, kw);
    k_zero_sumsq<<<(BB * NKVH * SS + 255) / 256, 256>>>();
    k_knorm<<<BB * NKVH * 16, 256>>>(hist, Wk);
    k_attn<<<BB * NKVH, 256>>>(hist, mask, Wv, out);
}

// round 3
// speedup vs baseline: 1.8771x; 1.8771x over previous
#include <cuda_runtime.h>
#include <cuda_bf16.h>
#include <math.h>
#include <stdint.h>

// Problem constants
#define BB   64
#define TT   8
#define DD   512
#define SS   512
#define NKVH 4
#define QK_SCALE 0.044194173824159216f
#define EPS 1e-6f

// ---------------------------------------------------------------------------
// Device-global scratch (no allocation allowed)
// ---------------------------------------------------------------------------
__device__ float g_q[BB * TT * DD];
__device__ float g_qt[BB * TT * DD];
__device__ float g_sumsq[BB * NKVH * SS];
__device__ int   g_mask_mode;
// bf16 split operands for tensor-core norm GEMM
__device__ __nv_bfloat16 g_hA [BB * SS * DD];   // hist hi
__device__ __nv_bfloat16 g_hAl[BB * SS * DD];   // hist lo
__device__ __nv_bfloat16 g_wB [NKVH * DD * DD]; // Wk hi
__device__ __nv_bfloat16 g_wBl[NKVH * DD * DD]; // Wk lo

// ---------------------------------------------------------------------------
// PTX helpers (sm_80-era only: cp.async + ldmatrix + mma.sync)
// ---------------------------------------------------------------------------
__device__ __forceinline__ uint32_t smem_u32(const void* p) {
    uint32_t a;
    asm("{ .reg .u64 t; cvta.to.shared.u64 t, %1; cvt.u32.u64 %0, t; }"
        : "=r"(a) : "l"(p));
    return a;
}
__device__ __forceinline__ void cp_async16(uint32_t dst, const void* src) {
    asm volatile("cp.async.cg.shared.global [%0], [%1], 16;"
                 :: "r"(dst), "l"(src));
}
#define CPASYNC_COMMIT() asm volatile("cp.async.commit_group;" ::: "memory")
#define CPASYNC_WAIT1()  asm volatile("cp.async.wait_group 1;" ::: "memory")
#define CPASYNC_WAIT0()  asm volatile("cp.async.wait_group 0;" ::: "memory")

__device__ __forceinline__ void ldmatrix_x4(uint32_t& r0, uint32_t& r1,
                                            uint32_t& r2, uint32_t& r3,
                                            uint32_t addr) {
    asm volatile("ldmatrix.sync.aligned.m8n8.x4.shared.b16 {%0,%1,%2,%3}, [%4];"
                 : "=r"(r0), "=r"(r1), "=r"(r2), "=r"(r3) : "r"(addr));
}
__device__ __forceinline__ void mma_bf16(float* d, const uint32_t* a,
                                         const uint32_t* b) {
    asm volatile(
        "mma.sync.aligned.m16n8k16.row.col.f32.bf16.bf16.f32 "
        "{%0,%1,%2,%3}, {%4,%5,%6,%7}, {%8,%9}, {%0,%1,%2,%3};"
        : "+f"(d[0]), "+f"(d[1]), "+f"(d[2]), "+f"(d[3])
        : "r"(a[0]), "r"(a[1]), "r"(a[2]), "r"(a[3]), "r"(b[0]), "r"(b[1]));
}

// ---------------------------------------------------------------------------
// Mask dtype sniffer
// ---------------------------------------------------------------------------
__global__ void k_detect_mask(const unsigned int* __restrict__ m) {
    __shared__ int flags[3];
    int tid = threadIdx.x;
    if (tid < 3) flags[tid] = 1;
    __syncthreads();
    int iok = 1, fok = 1, hok = 1;
    for (int i = tid; i < 8192; i += blockDim.x) {
        unsigned w = m[i];
        if (w > 1u) iok = 0;
        float f = __uint_as_float(w);
        if (!(f == 0.0f || f == 1.0f)) fok = 0;
        unsigned lo = w & 0xFFFFu, hi = w >> 16;
        if (!((lo == 0u || lo == 0x3F80u) && (hi == 0u || hi == 0x3F80u))) hok = 0;
    }
    if (!iok) atomicExch(&flags[0], 0);
    if (!fok) atomicExch(&flags[1], 0);
    if (!hok) atomicExch(&flags[2], 0);
    __syncthreads();
    if (tid == 0)
        g_mask_mode = flags[0] ? 0 : (flags[1] ? 1 : (flags[2] ? 3 : 2));
}
__device__ __forceinline__ bool is_masked(const void* m, int idx, int mode) {
    if (mode == 0) return ((const int*)m)[idx] != 0;
    if (mode == 1) return ((const float*)m)[idx] != 0.0f;
    if (mode == 3) return ((const unsigned short*)m)[idx] != 0;
    return ((const unsigned char*)m)[idx] != 0;
}

// ---------------------------------------------------------------------------
// bf16 hi/lo split precompute
// ---------------------------------------------------------------------------
__global__ void k_split(const float* __restrict__ src,
                        __nv_bfloat16* __restrict__ hi,
                        __nv_bfloat16* __restrict__ lo, int n4) {
    int i = blockIdx.x * blockDim.x + threadIdx.x;
    int stride = gridDim.x * blockDim.x;
    for (; i < n4; i += stride) {
        float4 v = ((const float4*)src)[i];
        __nv_bfloat16 h0 = __float2bfloat16_rn(v.x);
        __nv_bfloat16 h1 = __float2bfloat16_rn(v.y);
        __nv_bfloat16 h2 = __float2bfloat16_rn(v.z);
        __nv_bfloat16 h3 = __float2bfloat16_rn(v.w);
        __nv_bfloat16 l0 = __float2bfloat16_rn(v.x - __bfloat162float(h0));
        __nv_bfloat16 l1 = __float2bfloat16_rn(v.y - __bfloat162float(h1));
        __nv_bfloat16 l2 = __float2bfloat16_rn(v.z - __bfloat162float(h2));
        __nv_bfloat16 l3 = __float2bfloat16_rn(v.w - __bfloat162float(h3));
        ((__nv_bfloat162*)hi)[i * 2 + 0] = __halves2bfloat162(h0, h1);
        ((__nv_bfloat162*)hi)[i * 2 + 1] = __halves2bfloat162(h2, h3);
        ((__nv_bfloat162*)lo)[i * 2 + 0] = __halves2bfloat162(l0, l1);
        ((__nv_bfloat162*)lo)[i * 2 + 1] = __halves2bfloat162(l2, l3);
    }
}

// ---------------------------------------------------------------------------
// Q projection + RMSNorm: 128 blocks x 4 rows, 512 threads (e)
// ---------------------------------------------------------------------------
__global__ void __launch_bounds__(512) k_qproj(const float* __restrict__ tgt,
                                               const float* __restrict__ Wq,
                                               const float* __restrict__ qw) {
    int blk = blockIdx.x;
    int e = threadIdx.x;
    __shared__ float sx[4][DD];
    __shared__ float sred[512];
    for (int i = e; i < 4 * DD; i += 512)
        sx[i >> 9][i & 511] = tgt[(size_t)blk * 4 * DD + i];
    __syncthreads();
    const float4* w4 = (const float4*)(Wq + (size_t)e * DD);
    float acc[4] = {0.f, 0.f, 0.f, 0.f};
#pragma unroll 4
    for (int i = 0; i < DD / 4; i++) {
        float4 w = w4[i];
#pragma unroll
        for (int r = 0; r < 4; r++) {
            float4 x = ((const float4*)sx[r])[i];
            acc[r] += w.x * x.x + w.y * x.y + w.z * x.z + w.w * x.w;
        }
    }
    float wq1 = 1.0f + qw[e];
#pragma unroll
    for (int r = 0; r < 4; r++) {
        sred[e] = acc[r] * acc[r];
        __syncthreads();
        for (int off = 256; off > 0; off >>= 1) {
            if (e < off) sred[e] += sred[e + off];
            __syncthreads();
        }
        float inv = rsqrtf(sred[0] * (1.0f / (float)DD) + EPS);
        g_q[((size_t)blk * 4 + r) * DD + e] = acc[r] * inv * wq1;
        __syncthreads();
    }
}

// ---------------------------------------------------------------------------
// q-tilde: 128 blocks = n(4) x bpair(32); 4 rows (2 b x 2 t), 512 threads (d)
// ---------------------------------------------------------------------------
__global__ void __launch_bounds__(512) k_qtilde(const float* __restrict__ Wk,
                                                const float* __restrict__ kw) {
    int n  = blockIdx.x & 3;
    int bg = blockIdx.x >> 2;
    int d = threadIdx.x;
    __shared__ float sq[4][DD];
    float kw1 = 1.0f + kw[d];
#pragma unroll
    for (int r = 0; r < 4; r++) {
        int b = bg * 2 + (r >> 1);
        int t = n * 2 + (r & 1);
        sq[r][d] = g_q[((size_t)(b * TT + t)) * DD + d] * kw1;
    }
    __syncthreads();
    const float* wb = Wk + (size_t)(n * DD) * DD + d;
    float acc[4] = {0.f, 0.f, 0.f, 0.f};
#pragma unroll 4
    for (int e = 0; e < DD; e++) {
        float w = wb[(size_t)e * DD];
#pragma unroll
        for (int r = 0; r < 4; r++) acc[r] += sq[r][e] * w;
    }
#pragma unroll
    for (int r = 0; r < 4; r++) {
        int b = bg * 2 + (r >> 1);
        int t = n * 2 + (r & 1);
        g_qt[((size_t)(b * TT + t)) * DD + d] = acc[r] * QK_SCALE;
    }
}

// ---------------------------------------------------------------------------
__global__ void k_zero_sumsq() {
    int i = blockIdx.x * blockDim.x + threadIdx.x;
    if (i < BB * NKVH * SS) g_sumsq[i] = 0.0f;
}

// ---------------------------------------------------------------------------
// HMMA norm GEMM: C[s,e] = hist_b @ Wk_n^T via bf16 3-term split (logical
// K = 1536), row sum-of-squares atomically added into g_sumsq.
// CTA 128x128, Kstage=32, 3-stage cp.async, 256 threads (8 warps 4Mx2N),
// warp tile 32x64 via m16n8k16.  grid 4096 = b(64) x n(4) x stile(4) x etile(4).
// Smem rows padded to 80B -> conflict-free ldmatrix without swizzle.
// ---------------------------------------------------------------------------
#define KN_ROWB   80
#define KN_ATILE  (128 * KN_ROWB)            // 10240
#define KN_STAGE  (2 * KN_ATILE)             // 20480 (A then B)
#define KN_SMEM   (3 * KN_STAGE)             // 61440
#define KN_NSTAGE 48                         // 1536 / 32

__global__ void __launch_bounds__(256) k_knorm_hmma() {
    extern __shared__ __align__(16) char smem[];
    uint32_t sbase = smem_u32(smem);

    int tid = threadIdx.x;
    int wid = tid >> 5, lane = tid & 31;
    int warp_m = wid & 3;       // 4 warps along M (32 rows each)
    int warp_n = wid >> 2;      // 2 warps along N (64 cols each)

    int bx = blockIdx.x;
    int etile = bx & 3;
    int stile = (bx >> 2) & 3;
    int n = (bx >> 4) & 3;
    int b = bx >> 6;
    int s0 = stile * 128;
    int e0 = etile * 128;

    // segment operand bases (logical K = 3 x 512: hh, lh, hl)
    const __nv_bfloat16* Aseg[3];
    const __nv_bfloat16* Bseg[3];
    {
        const __nv_bfloat16* ah = g_hA  + (size_t)b * SS * DD;
        const __nv_bfloat16* al = g_hAl + (size_t)b * SS * DD;
        const __nv_bfloat16* bh = g_wB  + (size_t)n * DD * DD;
        const __nv_bfloat16* bl = g_wBl + (size_t)n * DD * DD;
        Aseg[0] = ah; Aseg[1] = al; Aseg[2] = ah;
        Bseg[0] = bh; Bseg[1] = bh; Bseg[2] = bl;
    }

    // loader mapping: 256 threads -> 128 rows x 2 halves; 2 chunks of 16B each
    int lrow = tid >> 1;
    int lhalf = tid & 1;
    size_t a_goff = (size_t)(s0 + lrow) * DD + lhalf * 16;
    size_t b_goff = (size_t)(e0 + lrow) * DD + lhalf * 16;
    uint32_t s_loff = (uint32_t)(lrow * KN_ROWB + lhalf * 32);

    // ldmatrix per-lane smem offsets
    int g = lane >> 3, lr = lane & 7;
    uint32_t a_off0, a_off1, b_off[4];
    {
        int a_row16 = ((g & 1) << 3) + lr;
        int a_kc = g >> 1;
        a_off0 = (uint32_t)((warp_m * 32 + a_row16) * KN_ROWB + a_kc * 16);
        a_off1 = a_off0 + 16 * KN_ROWB;
        int b_row16 = ((g >> 1) << 3) + lr;
        int b_kc = g & 1;
#pragma unroll
        for (int p = 0; p < 4; p++)
            b_off[p] = (uint32_t)(KN_ATILE +
                       (warp_n * 64 + p * 16 + b_row16) * KN_ROWB + b_kc * 16);
    }

    float acc[2][8][4];
#pragma unroll
    for (int mt = 0; mt < 2; mt++)
#pragma unroll
        for (int nt = 0; nt < 8; nt++)
#pragma unroll
            for (int c = 0; c < 4; c++) acc[mt][nt][c] = 0.0f;

    // stage loader
    auto load_stage = [&](int kt) {
        int seg = kt >> 4;
        int k0 = (kt & 15) * 32;
        uint32_t sb = sbase + (uint32_t)(kt % 3) * KN_STAGE;
        const __nv_bfloat16* as = Aseg[seg] + a_goff + k0;
        const __nv_bfloat16* bs = Bseg[seg] + b_goff + k0;
        cp_async16(sb + s_loff, as);
        cp_async16(sb + s_loff + 16, as + 8);
        cp_async16(sb + KN_ATILE + s_loff, bs);
        cp_async16(sb + KN_ATILE + s_loff + 16, bs + 8);
        CPASYNC_COMMIT();
    };

    load_stage(0);
    load_stage(1);

    for (int i = 0; i < KN_NSTAGE; i++) {
        if (i == KN_NSTAGE - 1) { CPASYNC_WAIT0(); } else { CPASYNC_WAIT1(); }
        __syncthreads();
        if (i + 2 < KN_NSTAGE) load_stage(i + 2);

        uint32_t sb = sbase + (uint32_t)(i % 3) * KN_STAGE;
#pragma unroll
        for (int ks = 0; ks < 2; ks++) {
            uint32_t koff = (uint32_t)(ks * 32);
            uint32_t afrag[2][4];
            uint32_t bfrag[8][2];
            ldmatrix_x4(afrag[0][0], afrag[0][1], afrag[0][2], afrag[0][3],
                        sb + a_off0 + koff);
            ldmatrix_x4(afrag[1][0], afrag[1][1], afrag[1][2], afrag[1][3],
                        sb + a_off1 + koff);
#pragma unroll
            for (int p = 0; p < 4; p++) {
                ldmatrix_x4(bfrag[2 * p][0], bfrag[2 * p][1],
                            bfrag[2 * p + 1][0], bfrag[2 * p + 1][1],
                            sb + b_off[p] + koff);
            }
#pragma unroll
            for (int mt = 0; mt < 2; mt++)
#pragma unroll
                for (int nt = 0; nt < 8; nt++)
                    mma_bf16(acc[mt][nt], afrag[mt], bfrag[nt]);
        }
        __syncthreads();
    }

    // epilogue: square, reduce across quad, atomicAdd per row
    size_t sbidx = ((size_t)(b * NKVH + n)) * SS + s0;
#pragma unroll
    for (int mt = 0; mt < 2; mt++) {
        float slo = 0.0f, shi = 0.0f;
#pragma unroll
        for (int nt = 0; nt < 8; nt++) {
            slo += acc[mt][nt][0] * acc[mt][nt][0] + acc[mt][nt][1] * acc[mt][nt][1];
            shi += acc[mt][nt][2] * acc[mt][nt][2] + acc[mt][nt][3] * acc[mt][nt][3];
        }
        slo += __shfl_xor_sync(0xFFFFFFFFu, slo, 1);
        slo += __shfl_xor_sync(0xFFFFFFFFu, slo, 2);
        shi += __shfl_xor_sync(0xFFFFFFFFu, shi, 1);
        shi += __shfl_xor_sync(0xFFFFFFFFu, shi, 2);
        if ((lane & 3) == 0) {
            int row = warp_m * 32 + mt * 16 + (lane >> 2);
            atomicAdd(&g_sumsq[sbidx + row], slo);
            atomicAdd(&g_sumsq[sbidx + row + 8], shi);
        }
    }
}

// ---------------------------------------------------------------------------
// Attention: scores -> softmax -> attn weights; ctx = attn@hist;
// tokens = ctx @ Wv_n^T.  One block per (b,n), 256 threads.
// ---------------------------------------------------------------------------
__global__ void __launch_bounds__(256) k_attn(const float* __restrict__ hist,
                                              const void*  __restrict__ mask,
                                              const float* __restrict__ Wv,
                                              float* __restrict__ out) {
    int b = blockIdx.x >> 2;
    int n = blockIdx.x & 3;
    int tid = threadIdx.x;
    int mode = g_mask_mode;

    __shared__ float sA[2][DD];
    __shared__ float ssc[2][SS];
    __shared__ float sred[256];

    for (int i = tid; i < 2 * DD; i += 256)
        sA[i >> 9][i & 511] = g_qt[((size_t)(b * TT + n * 2)) * DD + i];
    __syncthreads();

    for (int s = tid; s < SS; s += 256) {
        const float4* h4 = (const float4*)(hist + ((size_t)b * SS + s) * DD);
        const float4* a0 = (const float4*)sA[0];
        const float4* a1 = (const float4*)sA[1];
        float acc0 = 0.0f, acc1 = 0.0f;
#pragma unroll 8
        for (int i = 0; i < DD / 4; i++) {
            float4 h = h4[i];
            float4 x = a0[i];
            float4 y = a1[i];
            acc0 += h.x * x.x + h.y * x.y + h.z * x.z + h.w * x.w;
            acc1 += h.x * y.x + h.y * y.y + h.z * y.z + h.w * y.w;
        }
        float inv = rsqrtf(g_sumsq[((size_t)b * NKVH + n) * SS + s] * (1.0f / (float)DD) + EPS);
        bool msk = is_masked(mask, b * SS + s, mode);
        ssc[0][s] = msk ? -INFINITY : acc0 * inv;
        ssc[1][s] = msk ? -INFINITY : acc1 * inv;
    }
    __syncthreads();

    for (int g = 0; g < 2; g++) {
        float m = fmaxf(ssc[g][tid], ssc[g][tid + 256]);
        sred[tid] = m;
        __syncthreads();
        for (int off = 128; off > 0; off >>= 1) {
            if (tid < off) sred[tid] = fmaxf(sred[tid], sred[tid + off]);
            __syncthreads();
        }
        float rowmax = sred[0];
        __syncthreads();
        float e0 = expf(ssc[g][tid] - rowmax);
        float e1 = expf(ssc[g][tid + 256] - rowmax);
        sred[tid] = e0 + e1;
        __syncthreads();
        for (int off = 128; off > 0; off >>= 1) {
            if (tid < off) sred[tid] += sred[tid + off];
            __syncthreads();
        }
        float invsum = 1.0f / sred[0];
        __syncthreads();
        float a0 = e0 * invsum, a1 = e1 * invsum;
        ssc[g][tid] = a0;
        ssc[g][tid + 256] = a1;
        size_t wbase = (size_t)BB * TT * DD + ((size_t)(b * TT + n * 2 + g)) * SS;
        out[wbase + tid] = a0;
        out[wbase + tid + 256] = a1;
        __syncthreads();
    }

    for (int d = tid; d < DD; d += 256) {
        const float* hp = hist + (size_t)b * SS * DD + d;
        float c0 = 0.0f, c1 = 0.0f;
#pragma unroll 4
        for (int s = 0; s < SS; s++) {
            float h = hp[(size_t)s * DD];
            c0 += ssc[0][s] * h;
            c1 += ssc[1][s] * h;
        }
        sA[0][d] = c0;
        sA[1][d] = c1;
    }
    __syncthreads();

    for (int e = tid; e < DD; e += 256) {
        const float4* w4 = (const float4*)(Wv + ((size_t)(n * DD + e)) * DD);
        const float4* c0 = (const float4*)sA[0];
        const float4* c1 = (const float4*)sA[1];
        float o0 = 0.0f, o1 = 0.0f;
#pragma unroll 8
        for (int i = 0; i < DD / 4; i++) {
            float4 w = w4[i];
            float4 x = c0[i];
            float4 y = c1[i];
            o0 += w.x * x.x + w.y * x.y + w.z * x.z + w.w * x.w;
            o1 += w.x * y.x + w.y * y.y + w.z * y.z + w.w * y.w;
        }
        out[((size_t)(b * TT + n * 2 + 0)) * DD + e] = o0;
        out[((size_t)(b * TT + n * 2 + 1)) * DD + e] = o1;
    }
}

// ---------------------------------------------------------------------------
extern "C" void kernel_launch(void* const* d_in, const int* in_sizes, int n_in,
                              void* d_out, int out_size) {
    (void)in_sizes; (void)n_in; (void)out_size;
    const float* target = (const float*)d_in[0];
    const float* hist   = (const float*)d_in[1];
    const void*  mask   = d_in[2];
    const float* Wq     = (const float*)d_in[3];
    const float* Wk     = (const float*)d_in[4];
    const float* Wv     = (const float*)d_in[5];
    const float* qw     = (const float*)d_in[6];
    const float* kw     = (const float*)d_in[7];
    float* out = (float*)d_out;

    cudaFuncSetAttribute(k_knorm_hmma, cudaFuncAttributeMaxDynamicSharedMemorySize,
                         KN_SMEM);

    __nv_bfloat16 *hA, *hAl, *wB, *wBl;
    cudaGetSymbolAddress((void**)&hA,  g_hA);
    cudaGetSymbolAddress((void**)&hAl, g_hAl);
    cudaGetSymbolAddress((void**)&wB,  g_wB);
    cudaGetSymbolAddress((void**)&wBl, g_wBl);

    k_detect_mask<<<1, 256>>>((const unsigned int*)mask);
    k_split<<<2048, 256>>>(hist, hA, hAl, BB * SS * DD / 4);
    k_split<<<512, 256>>>(Wk, wB, wBl, NKVH * DD * DD / 4);
    k_qproj<<<128, 512>>>(target, Wq, qw);
    k_qtilde<<<128, 512>>>(Wk, kw);
    k_zero_sumsq<<<(BB * NKVH * SS + 255) / 256, 256>>>();
    k_knorm_hmma<<<BB * NKVH * 4 * 4, 256, KN_SMEM>>>();
    k_attn<<<BB * NKVH, 256>>>(hist, mask, Wv, out);
}

// round 5
// speedup vs baseline: 3.3571x; 1.7884x over previous
#include <cuda_runtime.h>
#include <cuda_fp16.h>
#include <math.h>
#include <stdint.h>

// Problem constants
#define BB   64
#define TT   8
#define DD   512
#define SS   512
#define NKVH 4
#define QK_SCALE 0.044194173824159216f
#define EPS 1e-6f

// ---------------------------------------------------------------------------
// Device-global scratch (no allocation allowed)
// ---------------------------------------------------------------------------
__device__ float g_q[BB * TT * DD];
__device__ float g_qt[BB * TT * DD];
__device__ float g_sumsq[BB * NKVH * SS];
__device__ int   g_mask_mode;
__device__ __half g_hH[BB * SS * DD];     // hist fp16
__device__ __half g_wH[NKVH * DD * DD];   // Wk fp16

// ---------------------------------------------------------------------------
// PTX helpers (sm_80-era: cp.async + ldmatrix + mma.sync)
// ---------------------------------------------------------------------------
__device__ __forceinline__ uint32_t smem_u32(const void* p) {
    uint32_t a;
    asm("{ .reg .u64 t; cvta.to.shared.u64 t, %1; cvt.u32.u64 %0, t; }"
        : "=r"(a) : "l"(p));
    return a;
}
__device__ __forceinline__ void cp_async16(uint32_t dst, const void* src) {
    asm volatile("cp.async.cg.shared.global [%0], [%1], 16;"
                 :: "r"(dst), "l"(src));
}
#define CPASYNC_COMMIT() asm volatile("cp.async.commit_group;" ::: "memory")
#define CPASYNC_WAIT1()  asm volatile("cp.async.wait_group 1;" ::: "memory")
#define CPASYNC_WAIT0()  asm volatile("cp.async.wait_group 0;" ::: "memory")

__device__ __forceinline__ void ldmatrix_x4(uint32_t& r0, uint32_t& r1,
                                            uint32_t& r2, uint32_t& r3,
                                            uint32_t addr) {
    asm volatile("ldmatrix.sync.aligned.m8n8.x4.shared.b16 {%0,%1,%2,%3}, [%4];"
                 : "=r"(r0), "=r"(r1), "=r"(r2), "=r"(r3) : "r"(addr));
}
__device__ __forceinline__ void mma_fp16(float* d, const uint32_t* a,
                                         const uint32_t* b) {
    asm volatile(
        "mma.sync.aligned.m16n8k16.row.col.f32.f16.f16.f32 "
        "{%0,%1,%2,%3}, {%4,%5,%6,%7}, {%8,%9}, {%0,%1,%2,%3};"
        : "+f"(d[0]), "+f"(d[1]), "+f"(d[2]), "+f"(d[3])
        : "r"(a[0]), "r"(a[1]), "r"(a[2]), "r"(a[3]), "r"(b[0]), "r"(b[1]));
}

// ---------------------------------------------------------------------------
// Mask dtype sniffer
// ---------------------------------------------------------------------------
__global__ void k_detect_mask(const unsigned int* __restrict__ m) {
    __shared__ int flags[3];
    int tid = threadIdx.x;
    if (tid < 3) flags[tid] = 1;
    __syncthreads();
    int iok = 1, fok = 1, hok = 1;
    for (int i = tid; i < 8192; i += blockDim.x) {
        unsigned w = m[i];
        if (w > 1u) iok = 0;
        float f = __uint_as_float(w);
        if (!(f == 0.0f || f == 1.0f)) fok = 0;
        unsigned lo = w & 0xFFFFu, hi = w >> 16;
        if (!((lo == 0u || lo == 0x3F80u) && (hi == 0u || hi == 0x3F80u))) hok = 0;
    }
    if (!iok) atomicExch(&flags[0], 0);
    if (!fok) atomicExch(&flags[1], 0);
    if (!hok) atomicExch(&flags[2], 0);
    __syncthreads();
    if (tid == 0)
        g_mask_mode = flags[0] ? 0 : (flags[1] ? 1 : (flags[2] ? 3 : 2));
}
__device__ __forceinline__ bool is_masked(const void* m, int idx, int mode) {
    if (mode == 0) return ((const int*)m)[idx] != 0;
    if (mode == 1) return ((const float*)m)[idx] != 0.0f;
    if (mode == 3) return ((const unsigned short*)m)[idx] != 0;
    return ((const unsigned char*)m)[idx] != 0;
}

// ---------------------------------------------------------------------------
// fp32 -> fp16 conversion
// ---------------------------------------------------------------------------
__global__ void k_tofp16(const float* __restrict__ src,
                         __half* __restrict__ dst, int n4) {
    int i = blockIdx.x * blockDim.x + threadIdx.x;
    int stride = gridDim.x * blockDim.x;
    for (; i < n4; i += stride) {
        float4 v = ((const float4*)src)[i];
        ((__half2*)dst)[i * 2 + 0] = __floats2half2_rn(v.x, v.y);
        ((__half2*)dst)[i * 2 + 1] = __floats2half2_rn(v.z, v.w);
    }
}

// ---------------------------------------------------------------------------
// Q projection + RMSNorm: 256 blocks x 2 rows, 512 threads (e)
// ---------------------------------------------------------------------------
__global__ void __launch_bounds__(512) k_qproj(const float* __restrict__ tgt,
                                               const float* __restrict__ Wq,
                                               const float* __restrict__ qw) {
    int blk = blockIdx.x;          // rows blk*2, blk*2+1
    int e = threadIdx.x;
    __shared__ float sx[2][DD];
    __shared__ float sred[512];
    for (int i = e; i < 2 * DD; i += 512)
        sx[i >> 9][i & 511] = tgt[(size_t)blk * 2 * DD + i];
    __syncthreads();
    const float4* w4 = (const float4*)(Wq + (size_t)e * DD);
    float acc0 = 0.f, acc1 = 0.f;
#pragma unroll 8
    for (int i = 0; i < DD / 4; i++) {
        float4 w = w4[i];
        float4 x = ((const float4*)sx[0])[i];
        float4 y = ((const float4*)sx[1])[i];
        acc0 += w.x * x.x + w.y * x.y + w.z * x.z + w.w * x.w;
        acc1 += w.x * y.x + w.y * y.y + w.z * y.z + w.w * y.w;
    }
    float wq1 = 1.0f + qw[e];
    float accs[2] = {acc0, acc1};
#pragma unroll
    for (int r = 0; r < 2; r++) {
        sred[e] = accs[r] * accs[r];
        __syncthreads();
        for (int off = 256; off > 0; off >>= 1) {
            if (e < off) sred[e] += sred[e + off];
            __syncthreads();
        }
        float inv = rsqrtf(sred[0] * (1.0f / (float)DD) + EPS);
        g_q[((size_t)blk * 2 + r) * DD + e] = accs[r] * inv * wq1;
        __syncthreads();
    }
}

// ---------------------------------------------------------------------------
// q-tilde: 128 blocks = n(4) x bpair(32); 4 rows, 512 threads (d)
// ---------------------------------------------------------------------------
__global__ void __launch_bounds__(512) k_qtilde(const float* __restrict__ Wk,
                                                const float* __restrict__ kw) {
    int n  = blockIdx.x & 3;
    int bg = blockIdx.x >> 2;
    int d = threadIdx.x;
    __shared__ float sq[4][DD];
    float kw1 = 1.0f + kw[d];
#pragma unroll
    for (int r = 0; r < 4; r++) {
        int b = bg * 2 + (r >> 1);
        int t = n * 2 + (r & 1);
        sq[r][d] = g_q[((size_t)(b * TT + t)) * DD + d] * kw1;
    }
    __syncthreads();
    const float* wb = Wk + (size_t)(n * DD) * DD + d;
    float acc[4] = {0.f, 0.f, 0.f, 0.f};
#pragma unroll 4
    for (int e = 0; e < DD; e++) {
        float w = wb[(size_t)e * DD];
#pragma unroll
        for (int r = 0; r < 4; r++) acc[r] += sq[r][e] * w;
    }
#pragma unroll
    for (int r = 0; r < 4; r++) {
        int b = bg * 2 + (r >> 1);
        int t = n * 2 + (r & 1);
        g_qt[((size_t)(b * TT + t)) * DD + d] = acc[r] * QK_SCALE;
    }
}

// ---------------------------------------------------------------------------
// fp16 HMMA norm GEMM: sumsq[s] = || hist_b[s,:] @ Wk_n^T ||^2.
// grid 1024 = b(64) x n(4) x stile(4).  A (128 s-rows x 512 K fp16) resident
// in smem (1040B row stride); B streamed per (etile, kstage=32) in 8KB stages
// (80B row stride), 3 slots.  Sumsq accumulates in regs across the 4 etiles;
// final reduce via smem — no global atomics.
// ---------------------------------------------------------------------------
#define KA_ROWB 1040
#define KA_BYTES (128 * KA_ROWB)             // 133120
#define KB_ROWB 80
#define KB_STAGE (128 * KB_ROWB)             // 10240
#define KN_SMEM (KA_BYTES + 3 * KB_STAGE)    // 163840
#define KN_ITERS 64                          // 4 etiles x 16 kstages

__global__ void __launch_bounds__(256) k_knorm_fp16() {
    extern __shared__ __align__(16) char smem[];
    uint32_t sbase = smem_u32(smem);

    int tid = threadIdx.x;
    int wid = tid >> 5, lane = tid & 31;
    int warp_m = wid & 3;       // 4 warps along M (32 rows each)
    int warp_n = wid >> 2;      // 2 warps along N (64 of 128 cols)

    int bx = blockIdx.x;
    int stile = bx & 3;
    int n = (bx >> 2) & 3;
    int b = bx >> 4;
    int s0 = stile * 128;

    const __half* Abase = g_hH + ((size_t)(b * SS + s0)) * DD;
    const __half* Bbase = g_wH + (size_t)n * DD * DD;

    // ---- A load: 128 rows x 1024B = 8192 x 16B chunks
    for (int m = tid; m < 8192; m += 256) {
        int row = m >> 6, seg = m & 63;
        cp_async16(sbase + (uint32_t)(row * KA_ROWB + seg * 16),
                   Abase + (size_t)row * DD + seg * 8);
    }
    CPASYNC_COMMIT();

    // ---- B stage loader: 128 e-rows x 64B = 512 x 16B chunks
    auto load_B = [&](int it) {
        int et = it >> 4;
        int k0 = (it & 15) * 32;
        uint32_t sb = sbase + KA_BYTES + (uint32_t)(it % 3) * KB_STAGE;
        const __half* src = Bbase + (size_t)(et * 128) * DD + k0;
#pragma unroll
        for (int c = 0; c < 2; c++) {
            int m = tid + c * 256;
            int row = m >> 2, seg = m & 3;
            cp_async16(sb + (uint32_t)(row * KB_ROWB + seg * 16),
                       src + (size_t)row * DD + seg * 8);
        }
        CPASYNC_COMMIT();
    };
    load_B(0);
    load_B(1);

    // ldmatrix per-lane offsets
    int g = lane >> 3, lr = lane & 7;
    int a_row16 = ((g & 1) << 3) + lr;
    int a_kc = g >> 1;
    uint32_t a_off0 = (uint32_t)((warp_m * 32 + a_row16) * KA_ROWB + a_kc * 16);
    uint32_t a_off1 = a_off0 + 16 * KA_ROWB;
    int b_row16 = ((g >> 1) << 3) + lr;
    int b_kc = g & 1;
    uint32_t b_off[4];
#pragma unroll
    for (int p = 0; p < 4; p++)
        b_off[p] = (uint32_t)((warp_n * 64 + p * 16 + b_row16) * KB_ROWB + b_kc * 16);

    float acc[2][8][4];
#pragma unroll
    for (int mt = 0; mt < 2; mt++)
#pragma unroll
        for (int nt = 0; nt < 8; nt++)
#pragma unroll
            for (int c = 0; c < 4; c++) acc[mt][nt][c] = 0.0f;
    float rs[2][2] = {{0.f, 0.f}, {0.f, 0.f}};  // [mt][lo/hi row]

    for (int it = 0; it < KN_ITERS; it++) {
        if (it == KN_ITERS - 1) { CPASYNC_WAIT0(); } else { CPASYNC_WAIT1(); }
        __syncthreads();
        if (it + 2 < KN_ITERS) load_B(it + 2);

        uint32_t akb = sbase + (uint32_t)((it & 15) * 64);
        uint32_t bsb = sbase + KA_BYTES + (uint32_t)(it % 3) * KB_STAGE;
#pragma unroll
        for (int ks = 0; ks < 2; ks++) {
            uint32_t koff = (uint32_t)(ks * 32);
            uint32_t afrag[2][4];
            uint32_t bfrag[8][2];
            ldmatrix_x4(afrag[0][0], afrag[0][1], afrag[0][2], afrag[0][3],
                        akb + a_off0 + koff);
            ldmatrix_x4(afrag[1][0], afrag[1][1], afrag[1][2], afrag[1][3],
                        akb + a_off1 + koff);
#pragma unroll
            for (int p = 0; p < 4; p++) {
                ldmatrix_x4(bfrag[2 * p][0], bfrag[2 * p][1],
                            bfrag[2 * p + 1][0], bfrag[2 * p + 1][1],
                            bsb + b_off[p] + koff);
            }
#pragma unroll
            for (int mt = 0; mt < 2; mt++)
#pragma unroll
                for (int nt = 0; nt < 8; nt++)
                    mma_fp16(acc[mt][nt], afrag[mt], bfrag[nt]);
        }

        if ((it & 15) == 15) {   // etile finished: fold squares, reset acc
#pragma unroll
            for (int mt = 0; mt < 2; mt++) {
#pragma unroll
                for (int nt = 0; nt < 8; nt++) {
                    rs[mt][0] += acc[mt][nt][0] * acc[mt][nt][0]
                               + acc[mt][nt][1] * acc[mt][nt][1];
                    rs[mt][1] += acc[mt][nt][2] * acc[mt][nt][2]
                               + acc[mt][nt][3] * acc[mt][nt][3];
                    acc[mt][nt][0] = acc[mt][nt][1] = 0.f;
                    acc[mt][nt][2] = acc[mt][nt][3] = 0.f;
                }
            }
        }
        __syncthreads();
    }

    // quad reduce (cols within thread-quad)
#pragma unroll
    for (int mt = 0; mt < 2; mt++) {
#pragma unroll
        for (int h = 0; h < 2; h++) {
            rs[mt][h] += __shfl_xor_sync(0xFFFFFFFFu, rs[mt][h], 1);
            rs[mt][h] += __shfl_xor_sync(0xFFFFFFFFu, rs[mt][h], 2);
        }
    }
    // cross-warp (warp_n 0/1) reduce via smem
    float* ssum = (float*)smem;
    if (tid < 128) ssum[tid] = 0.0f;
    __syncthreads();
    if ((lane & 3) == 0) {
        int rbase = warp_m * 32 + (lane >> 2);
#pragma unroll
        for (int mt = 0; mt < 2; mt++) {
            atomicAdd(&ssum[rbase + mt * 16], rs[mt][0]);
            atomicAdd(&ssum[rbase + mt * 16 + 8], rs[mt][1]);
        }
    }
    __syncthreads();
    if (tid < 128)
        g_sumsq[((size_t)(b * NKVH + n)) * SS + s0 + tid] = ssum[tid];
}

// ---------------------------------------------------------------------------
// Attention: scores -> softmax -> attn weights; ctx = attn@hist;
// tokens = ctx @ Wv_n^T.  One block per (b,n), 256 threads.
// ---------------------------------------------------------------------------
__global__ void __launch_bounds__(256) k_attn(const float* __restrict__ hist,
                                              const void*  __restrict__ mask,
                                              const float* __restrict__ Wv,
                                              float* __restrict__ out) {
    int b = blockIdx.x >> 2;
    int n = blockIdx.x & 3;
    int tid = threadIdx.x;
    int mode = g_mask_mode;

    __shared__ float sA[2][DD];
    __shared__ float ssc[2][SS];
    __shared__ float sred[256];

    for (int i = tid; i < 2 * DD; i += 256)
        sA[i >> 9][i & 511] = g_qt[((size_t)(b * TT + n * 2)) * DD + i];
    __syncthreads();

    for (int s = tid; s < SS; s += 256) {
        const float4* h4 = (const float4*)(hist + ((size_t)b * SS + s) * DD);
        const float4* a0 = (const float4*)sA[0];
        const float4* a1 = (const float4*)sA[1];
        float acc0 = 0.0f, acc1 = 0.0f;
#pragma unroll 8
        for (int i = 0; i < DD / 4; i++) {
            float4 h = h4[i];
            float4 x = a0[i];
            float4 y = a1[i];
            acc0 += h.x * x.x + h.y * x.y + h.z * x.z + h.w * x.w;
            acc1 += h.x * y.x + h.y * y.y + h.z * y.z + h.w * y.w;
        }
        float inv = rsqrtf(g_sumsq[((size_t)b * NKVH + n) * SS + s] * (1.0f / (float)DD) + EPS);
        bool msk = is_masked(mask, b * SS + s, mode);
        ssc[0][s] = msk ? -INFINITY : acc0 * inv;
        ssc[1][s] = msk ? -INFINITY : acc1 * inv;
    }
    __syncthreads();

    for (int g = 0; g < 2; g++) {
        float m = fmaxf(ssc[g][tid], ssc[g][tid + 256]);
        sred[tid] = m;
        __syncthreads();
        for (int off = 128; off > 0; off >>= 1) {
            if (tid < off) sred[tid] = fmaxf(sred[tid], sred[tid + off]);
            __syncthreads();
        }
        float rowmax = sred[0];
        __syncthreads();
        float e0 = expf(ssc[g][tid] - rowmax);
        float e1 = expf(ssc[g][tid + 256] - rowmax);
        sred[tid] = e0 + e1;
        __syncthreads();
        for (int off = 128; off > 0; off >>= 1) {
            if (tid < off) sred[tid] += sred[tid + off];
            __syncthreads();
        }
        float invsum = 1.0f / sred[0];
        __syncthreads();
        float a0 = e0 * invsum, a1 = e1 * invsum;
        ssc[g][tid] = a0;
        ssc[g][tid + 256] = a1;
        size_t wbase = (size_t)BB * TT * DD + ((size_t)(b * TT + n * 2 + g)) * SS;
        out[wbase + tid] = a0;
        out[wbase + tid + 256] = a1;
        __syncthreads();
    }

    for (int d = tid; d < DD; d += 256) {
        const float* hp = hist + (size_t)b * SS * DD + d;
        float c0 = 0.0f, c1 = 0.0f;
#pragma unroll 4
        for (int s = 0; s < SS; s++) {
            float h = hp[(size_t)s * DD];
            c0 += ssc[0][s] * h;
            c1 += ssc[1][s] * h;
        }
        sA[0][d] = c0;
        sA[1][d] = c1;
    }
    __syncthreads();

    for (int e = tid; e < DD; e += 256) {
        const float4* w4 = (const float4*)(Wv + ((size_t)(n * DD + e)) * DD);
        const float4* c0 = (const float4*)sA[0];
        const float4* c1 = (const float4*)sA[1];
        float o0 = 0.0f, o1 = 0.0f;
#pragma unroll 8
        for (int i = 0; i < DD / 4; i++) {
            float4 w = w4[i];
            float4 x = c0[i];
            float4 y = c1[i];
            o0 += w.x * x.x + w.y * x.y + w.z * x.z + w.w * x.w;
            o1 += w.x * y.x + w.y * y.y + w.z * y.z + w.w * y.w;
        }
        out[((size_t)(b * TT + n * 2 + 0)) * DD + e] = o0;
        out[((size_t)(b * TT + n * 2 + 1)) * DD + e] = o1;
    }
}

// ---------------------------------------------------------------------------
extern "C" void kernel_launch(void* const* d_in, const int* in_sizes, int n_in,
                              void* d_out, int out_size) {
    (void)in_sizes; (void)n_in; (void)out_size;
    const float* target = (const float*)d_in[0];
    const float* hist   = (const float*)d_in[1];
    const void*  mask   = d_in[2];
    const float* Wq     = (const float*)d_in[3];
    const float* Wk     = (const float*)d_in[4];
    const float* Wv     = (const float*)d_in[5];
    const float* qw     = (const float*)d_in[6];
    const float* kw     = (const float*)d_in[7];
    float* out = (float*)d_out;

    cudaFuncSetAttribute(k_knorm_fp16, cudaFuncAttributeMaxDynamicSharedMemorySize,
                         KN_SMEM);

    __half *hH, *wH;
    cudaGetSymbolAddress((void**)&hH, g_hH);
    cudaGetSymbolAddress((void**)&wH, g_wH);

    k_detect_mask<<<1, 256>>>((const unsigned int*)mask);
    k_tofp16<<<2048, 256>>>(hist, hH, BB * SS * DD / 4);
    k_tofp16<<<512, 256>>>(Wk, wH, NKVH * DD * DD / 4);
    k_qproj<<<256, 512>>>(target, Wq, qw);
    k_qtilde<<<128, 512>>>(Wk, kw);
    k_knorm_fp16<<<BB * NKVH * 4, 256, KN_SMEM>>>();
    k_attn<<<BB * NKVH, 256>>>(hist, mask, Wv, out);
}

// round 6
// speedup vs baseline: 3.6825x; 1.0969x over previous
#include <cuda_runtime.h>
#include <cuda_fp16.h>
#include <math.h>
#include <stdint.h>

// Problem constants
#define BB   64
#define TT   8
#define DD   512
#define SS   512
#define NKVH 4
#define QK_SCALE 0.044194173824159216f
#define EPS 1e-6f

// ---------------------------------------------------------------------------
// Device-global scratch (no allocation allowed)
// ---------------------------------------------------------------------------
__device__ float g_q[BB * TT * DD];        // RAW q projection (pre-norm)
__device__ float g_qt[BB * TT * DD];       // q-tilde
__device__ float g_sumsq[BB * NKVH * SS];
__device__ float g_ctx[BB * TT * DD];      // attn @ hist
__device__ int   g_mask_mode;
__device__ __half g_hH[BB * SS * DD];      // hist fp16
__device__ __half g_wH[NKVH * DD * DD];    // Wk fp16

// ---------------------------------------------------------------------------
// PTX helpers (sm_80-era: cp.async + ldmatrix + mma.sync)
// ---------------------------------------------------------------------------
__device__ __forceinline__ uint32_t smem_u32(const void* p) {
    uint32_t a;
    asm("{ .reg .u64 t; cvta.to.shared.u64 t, %1; cvt.u32.u64 %0, t; }"
        : "=r"(a) : "l"(p));
    return a;
}
__device__ __forceinline__ void cp_async16(uint32_t dst, const void* src) {
    asm volatile("cp.async.cg.shared.global [%0], [%1], 16;"
                 :: "r"(dst), "l"(src));
}
#define CPASYNC_COMMIT() asm volatile("cp.async.commit_group;" ::: "memory")
#define CPASYNC_WAIT1()  asm volatile("cp.async.wait_group 1;" ::: "memory")
#define CPASYNC_WAIT0()  asm volatile("cp.async.wait_group 0;" ::: "memory")

__device__ __forceinline__ void ldmatrix_x4(uint32_t& r0, uint32_t& r1,
                                            uint32_t& r2, uint32_t& r3,
                                            uint32_t addr) {
    asm volatile("ldmatrix.sync.aligned.m8n8.x4.shared.b16 {%0,%1,%2,%3}, [%4];"
                 : "=r"(r0), "=r"(r1), "=r"(r2), "=r"(r3) : "r"(addr));
}
__device__ __forceinline__ void mma_fp16(float* d, const uint32_t* a,
                                         const uint32_t* b) {
    asm volatile(
        "mma.sync.aligned.m16n8k16.row.col.f32.f16.f16.f32 "
        "{%0,%1,%2,%3}, {%4,%5,%6,%7}, {%8,%9}, {%0,%1,%2,%3};"
        : "+f"(d[0]), "+f"(d[1]), "+f"(d[2]), "+f"(d[3])
        : "r"(a[0]), "r"(a[1]), "r"(a[2]), "r"(a[3]), "r"(b[0]), "r"(b[1]));
}

// ---------------------------------------------------------------------------
// Mask dtype sniffer
// ---------------------------------------------------------------------------
__global__ void k_detect_mask(const unsigned int* __restrict__ m) {
    __shared__ int flags[3];
    int tid = threadIdx.x;
    if (tid < 3) flags[tid] = 1;
    __syncthreads();
    int iok = 1, fok = 1, hok = 1;
    for (int i = tid; i < 8192; i += blockDim.x) {
        unsigned w = m[i];
        if (w > 1u) iok = 0;
        float f = __uint_as_float(w);
        if (!(f == 0.0f || f == 1.0f)) fok = 0;
        unsigned lo = w & 0xFFFFu, hi = w >> 16;
        if (!((lo == 0u || lo == 0x3F80u) && (hi == 0u || hi == 0x3F80u))) hok = 0;
    }
    if (!iok) atomicExch(&flags[0], 0);
    if (!fok) atomicExch(&flags[1], 0);
    if (!hok) atomicExch(&flags[2], 0);
    __syncthreads();
    if (tid == 0)
        g_mask_mode = flags[0] ? 0 : (flags[1] ? 1 : (flags[2] ? 3 : 2));
}
__device__ __forceinline__ bool is_masked(const void* m, int idx, int mode) {
    if (mode == 0) return ((const int*)m)[idx] != 0;
    if (mode == 1) return ((const float*)m)[idx] != 0.0f;
    if (mode == 3) return ((const unsigned short*)m)[idx] != 0;
    return ((const unsigned char*)m)[idx] != 0;
}

// ---------------------------------------------------------------------------
// fp32 -> fp16 conversion
// ---------------------------------------------------------------------------
__global__ void k_tofp16(const float* __restrict__ src,
                         __half* __restrict__ dst, int n4) {
    int i = blockIdx.x * blockDim.x + threadIdx.x;
    int stride = gridDim.x * blockDim.x;
    for (; i < n4; i += stride) {
        float4 v = ((const float4*)src)[i];
        ((__half2*)dst)[i * 2 + 0] = __floats2half2_rn(v.x, v.y);
        ((__half2*)dst)[i * 2 + 1] = __floats2half2_rn(v.z, v.w);
    }
}

// ---------------------------------------------------------------------------
// Raw Q projection as coalesced tiled SGEMM: g_q[m,e] = tgt[m,:] . Wq[e,:]
// 64x64 tiles, grid 64 = mt(8) x nt(8), 256 threads, K streamed 16, double buf.
// ---------------------------------------------------------------------------
__global__ void __launch_bounds__(256) k_qproj_gemm(const float* __restrict__ tgt,
                                                    const float* __restrict__ Wq) {
    __shared__ float As[2][16][68];
    __shared__ float Bs[2][16][68];
    int tid = threadIdx.x;
    int m0 = (blockIdx.x >> 3) * 64;
    int e0 = (blockIdx.x & 7) * 64;

    int lrow = tid >> 2;            // 0..63
    int lkc  = (tid & 3) * 4;       // 0,4,8,12
    int trow = tid >> 4;            // 0..15
    int tcol = tid & 15;            // 0..15

    float acc[4][4];
#pragma unroll
    for (int i = 0; i < 4; i++)
#pragma unroll
        for (int j = 0; j < 4; j++) acc[i][j] = 0.0f;

    float4 ra = *(const float4*)(tgt + (size_t)(m0 + lrow) * DD + lkc);
    float4 rb = *(const float4*)(Wq  + (size_t)(e0 + lrow) * DD + lkc);
#pragma unroll
    for (int j = 0; j < 4; j++) {
        As[0][lkc + j][lrow] = ((const float*)&ra)[j];
        Bs[0][lkc + j][lrow] = ((const float*)&rb)[j];
    }
    __syncthreads();

    for (int s = 0; s < 32; s++) {
        int buf = s & 1;
        if (s + 1 < 32) {
            int k0 = (s + 1) * 16;
            ra = *(const float4*)(tgt + (size_t)(m0 + lrow) * DD + k0 + lkc);
            rb = *(const float4*)(Wq  + (size_t)(e0 + lrow) * DD + k0 + lkc);
        }
#pragma unroll
        for (int k = 0; k < 16; k++) {
            float ar[4], br[4];
            *(float4*)ar = *(const float4*)&As[buf][k][trow * 4];
            *(float4*)br = *(const float4*)&Bs[buf][k][tcol * 4];
#pragma unroll
            for (int i = 0; i < 4; i++)
#pragma unroll
                for (int j = 0; j < 4; j++) acc[i][j] += ar[i] * br[j];
        }
        if (s + 1 < 32) {
            __syncthreads();
#pragma unroll
            for (int j = 0; j < 4; j++) {
                As[buf ^ 1][lkc + j][lrow] = ((const float*)&ra)[j];
                Bs[buf ^ 1][lkc + j][lrow] = ((const float*)&rb)[j];
            }
            __syncthreads();
        }
    }
#pragma unroll
    for (int i = 0; i < 4; i++)
        *(float4*)&g_q[(size_t)(m0 + trow * 4 + i) * DD + e0 + tcol * 4] =
            *(float4*)acc[i];
}

// ---------------------------------------------------------------------------
// q-tilde with fused RMS-norm: 128 blocks = n(4) x bpair(32); 4 rows, 512 thr
// q'[e] = qraw[e]*inv_rms*(1+qw[e])*(1+kw[e]);  qt[d] = sum_e q'[e] Wk[n,e,d]
// ---------------------------------------------------------------------------
__global__ void __launch_bounds__(512) k_qtilde(const float* __restrict__ Wk,
                                                const float* __restrict__ qw,
                                                const float* __restrict__ kw) {
    int n  = blockIdx.x & 3;
    int bg = blockIdx.x >> 2;
    int d = threadIdx.x;
    __shared__ float sq[4][DD];
    __shared__ float sred[512];
    float wprod = (1.0f + qw[d]) * (1.0f + kw[d]);
#pragma unroll
    for (int r = 0; r < 4; r++) {
        int b = bg * 2 + (r >> 1);
        int t = n * 2 + (r & 1);
        sq[r][d] = g_q[((size_t)(b * TT + t)) * DD + d];
    }
    __syncthreads();
#pragma unroll
    for (int r = 0; r < 4; r++) {
        float v = sq[r][d];
        sred[d] = v * v;
        __syncthreads();
        for (int off = 256; off > 0; off >>= 1) {
            if (d < off) sred[d] += sred[d + off];
            __syncthreads();
        }
        float inv = rsqrtf(sred[0] * (1.0f / (float)DD) + EPS);
        __syncthreads();
        sq[r][d] = v * inv * wprod;
    }
    __syncthreads();
    const float* wb = Wk + (size_t)(n * DD) * DD + d;
    float acc[4] = {0.f, 0.f, 0.f, 0.f};
#pragma unroll 4
    for (int e = 0; e < DD; e++) {
        float w = wb[(size_t)e * DD];
#pragma unroll
        for (int r = 0; r < 4; r++) acc[r] += sq[r][e] * w;
    }
#pragma unroll
    for (int r = 0; r < 4; r++) {
        int b = bg * 2 + (r >> 1);
        int t = n * 2 + (r & 1);
        g_qt[((size_t)(b * TT + t)) * DD + d] = acc[r] * QK_SCALE;
    }
}

// ---------------------------------------------------------------------------
// fp16 HMMA norm GEMM, 512 threads / 16 warps for issue hiding.
// grid 1024 = b(64) x n(4) x stile(4).  A (128 x 512 fp16) smem-resident,
// B streamed in 8KB k-stages (3 slots).  Warp tile 32x32 (4M x 4N warps).
// ---------------------------------------------------------------------------
#define KA_ROWB 1040
#define KA_BYTES (128 * KA_ROWB)             // 133120
#define KB_ROWB 80
#define KB_STAGE (128 * KB_ROWB)             // 10240
#define KN_SMEM (KA_BYTES + 3 * KB_STAGE)    // 163840
#define KN_ITERS 64                          // 4 etiles x 16 kstages

__global__ void __launch_bounds__(512) k_knorm_fp16() {
    extern __shared__ __align__(16) char smem[];
    uint32_t sbase = smem_u32(smem);

    int tid = threadIdx.x;
    int wid = tid >> 5, lane = tid & 31;
    int warp_m = wid & 3;       // 4 warps along M (32 rows each)
    int warp_n = wid >> 2;      // 4 warps along N (32 of 128 cols)

    int bx = blockIdx.x;
    int stile = bx & 3;
    int n = (bx >> 2) & 3;
    int b = bx >> 4;
    int s0 = stile * 128;

    const __half* Abase = g_hH + ((size_t)(b * SS + s0)) * DD;
    const __half* Bbase = g_wH + (size_t)n * DD * DD;

    // A load: 128 rows x 1024B = 8192 x 16B chunks, 16 per thread
    for (int m = tid; m < 8192; m += 512) {
        int row = m >> 6, seg = m & 63;
        cp_async16(sbase + (uint32_t)(row * KA_ROWB + seg * 16),
                   Abase + (size_t)row * DD + seg * 8);
    }
    CPASYNC_COMMIT();

    auto load_B = [&](int it) {
        int et = it >> 4;
        int k0 = (it & 15) * 32;
        uint32_t sb = sbase + KA_BYTES + (uint32_t)(it % 3) * KB_STAGE;
        const __half* src = Bbase + (size_t)(et * 128) * DD + k0;
        int row = tid >> 2, seg = tid & 3;   // 512 chunks, 1 per thread
        cp_async16(sb + (uint32_t)(row * KB_ROWB + seg * 16),
                   src + (size_t)row * DD + seg * 8);
        CPASYNC_COMMIT();
    };
    load_B(0);
    load_B(1);

    // ldmatrix per-lane offsets
    int g = lane >> 3, lr = lane & 7;
    int a_row16 = ((g & 1) << 3) + lr;
    int a_kc = g >> 1;
    uint32_t a_off0 = (uint32_t)((warp_m * 32 + a_row16) * KA_ROWB + a_kc * 16);
    uint32_t a_off1 = a_off0 + 16 * KA_ROWB;
    int b_row16 = ((g >> 1) << 3) + lr;
    int b_kc = g & 1;
    uint32_t b_off[2];
#pragma unroll
    for (int p = 0; p < 2; p++)
        b_off[p] = (uint32_t)((warp_n * 32 + p * 16 + b_row16) * KB_ROWB + b_kc * 16);

    float acc[2][4][4];
#pragma unroll
    for (int mt = 0; mt < 2; mt++)
#pragma unroll
        for (int nt = 0; nt < 4; nt++)
#pragma unroll
            for (int c = 0; c < 4; c++) acc[mt][nt][c] = 0.0f;
    float rs[2][2] = {{0.f, 0.f}, {0.f, 0.f}};

    for (int it = 0; it < KN_ITERS; it++) {
        if (it == KN_ITERS - 1) { CPASYNC_WAIT0(); } else { CPASYNC_WAIT1(); }
        __syncthreads();
        if (it + 2 < KN_ITERS) load_B(it + 2);

        uint32_t akb = sbase + (uint32_t)((it & 15) * 64);
        uint32_t bsb = sbase + KA_BYTES + (uint32_t)(it % 3) * KB_STAGE;
#pragma unroll
        for (int ks = 0; ks < 2; ks++) {
            uint32_t koff = (uint32_t)(ks * 32);
            uint32_t afrag[2][4];
            uint32_t bfrag[4][2];
            ldmatrix_x4(afrag[0][0], afrag[0][1], afrag[0][2], afrag[0][3],
                        akb + a_off0 + koff);
            ldmatrix_x4(afrag[1][0], afrag[1][1], afrag[1][2], afrag[1][3],
                        akb + a_off1 + koff);
#pragma unroll
            for (int p = 0; p < 2; p++) {
                ldmatrix_x4(bfrag[2 * p][0], bfrag[2 * p][1],
                            bfrag[2 * p + 1][0], bfrag[2 * p + 1][1],
                            bsb + b_off[p] + koff);
            }
#pragma unroll
            for (int mt = 0; mt < 2; mt++)
#pragma unroll
                for (int nt = 0; nt < 4; nt++)
                    mma_fp16(acc[mt][nt], afrag[mt], bfrag[nt]);
        }

        if ((it & 15) == 15) {   // etile done: fold squares, reset acc
#pragma unroll
            for (int mt = 0; mt < 2; mt++) {
#pragma unroll
                for (int nt = 0; nt < 4; nt++) {
                    rs[mt][0] += acc[mt][nt][0] * acc[mt][nt][0]
                               + acc[mt][nt][1] * acc[mt][nt][1];
                    rs[mt][1] += acc[mt][nt][2] * acc[mt][nt][2]
                               + acc[mt][nt][3] * acc[mt][nt][3];
                    acc[mt][nt][0] = acc[mt][nt][1] = 0.f;
                    acc[mt][nt][2] = acc[mt][nt][3] = 0.f;
                }
            }
        }
    }

    // quad reduce (cols within thread-quad)
#pragma unroll
    for (int mt = 0; mt < 2; mt++) {
#pragma unroll
        for (int h = 0; h < 2; h++) {
            rs[mt][h] += __shfl_xor_sync(0xFFFFFFFFu, rs[mt][h], 1);
            rs[mt][h] += __shfl_xor_sync(0xFFFFFFFFu, rs[mt][h], 2);
        }
    }
    __syncthreads();
    float* ssum = (float*)smem;
    if (tid < 128) ssum[tid] = 0.0f;
    __syncthreads();
    if ((lane & 3) == 0) {
        int rbase = warp_m * 32 + (lane >> 2);
#pragma unroll
        for (int mt = 0; mt < 2; mt++) {
            atomicAdd(&ssum[rbase + mt * 16], rs[mt][0]);
            atomicAdd(&ssum[rbase + mt * 16 + 8], rs[mt][1]);
        }
    }
    __syncthreads();
    if (tid < 128)
        g_sumsq[((size_t)(b * NKVH + n)) * SS + s0 + tid] = ssum[tid];
}

// ---------------------------------------------------------------------------
// Attention (scores + softmax + ctx), all 4 heads per block.
// grid 64 = b, 512 threads / 16 warps.  Writes attn weights + g_ctx.
// ---------------------------------------------------------------------------
__global__ void __launch_bounds__(512) k_attn2(const float* __restrict__ hist,
                                               const void*  __restrict__ mask,
                                               float* __restrict__ out) {
    int b = blockIdx.x;
    int tid = threadIdx.x;
    int wid = tid >> 5, lane = tid & 31;
    int mode = g_mask_mode;

    __shared__ float sqt[TT][DD];    // 16KB
    __shared__ float ssc[TT][SS];    // 16KB

    for (int i = tid; i < TT * DD; i += 512)
        sqt[i >> 9][i & 511] = g_qt[(size_t)(b * TT) * DD + i];
    __syncthreads();

    // ---- scores: warp w owns rows [w*32, w*32+32)
    for (int r = 0; r < 32; r++) {
        int s = wid * 32 + r;
        const float4* hp = (const float4*)(hist + ((size_t)(b * SS + s)) * DD);
        float4 h[4];
#pragma unroll
        for (int i = 0; i < 4; i++) h[i] = hp[lane + 32 * i];
        float p[TT];
#pragma unroll
        for (int t = 0; t < TT; t++) {
            const float4* q4 = (const float4*)sqt[t];
            float a = 0.0f;
#pragma unroll
            for (int i = 0; i < 4; i++) {
                float4 q = q4[lane + 32 * i];
                a += q.x * h[i].x + q.y * h[i].y + q.z * h[i].z + q.w * h[i].w;
            }
            p[t] = a;
        }
#pragma unroll
        for (int off = 16; off > 0; off >>= 1)
#pragma unroll
            for (int t = 0; t < TT; t++)
                p[t] += __shfl_xor_sync(0xFFFFFFFFu, p[t], off);
        if (lane == 0) {
            bool mk = is_masked(mask, b * SS + s, mode);
#pragma unroll
            for (int n = 0; n < NKVH; n++) {
                float inv = rsqrtf(g_sumsq[((size_t)(b * NKVH + n)) * SS + s]
                                   * (1.0f / (float)DD) + EPS);
                ssc[n * 2][s]     = mk ? -INFINITY : p[n * 2] * inv;
                ssc[n * 2 + 1][s] = mk ? -INFINITY : p[n * 2 + 1] * inv;
            }
        }
    }
    __syncthreads();

    // ---- softmax: warp t (0..7) owns row t
    if (wid < TT) {
        int t = wid;
        float v[16];
        float mx = -INFINITY;
#pragma unroll
        for (int j = 0; j < 16; j++) {
            v[j] = ssc[t][lane + 32 * j];
            mx = fmaxf(mx, v[j]);
        }
#pragma unroll
        for (int off = 16; off > 0; off >>= 1)
            mx = fmaxf(mx, __shfl_xor_sync(0xFFFFFFFFu, mx, off));
        float sum = 0.0f;
#pragma unroll
        for (int j = 0; j < 16; j++) { v[j] = expf(v[j] - mx); sum += v[j]; }
#pragma unroll
        for (int off = 16; off > 0; off >>= 1)
            sum += __shfl_xor_sync(0xFFFFFFFFu, sum, off);
        float is = 1.0f / sum;
        size_t wbase = (size_t)BB * TT * DD + ((size_t)(b * TT + t)) * SS;
#pragma unroll
        for (int j = 0; j < 16; j++) {
            float a = v[j] * is;
            ssc[t][lane + 32 * j] = a;
            out[wbase + lane + 32 * j] = a;
        }
    }
    __syncthreads();

    // ---- ctx[t][d] = sum_s attn[t][s] * hist[b,s,d]
    int d = tid;
    float acc[TT];
#pragma unroll
    for (int t = 0; t < TT; t++) acc[t] = 0.0f;
    const float* hp = hist + (size_t)b * SS * DD + d;
    for (int s0 = 0; s0 < SS; s0 += 4) {
        float h0 = hp[(size_t)s0 * DD];
        float h1 = hp[(size_t)(s0 + 1) * DD];
        float h2 = hp[(size_t)(s0 + 2) * DD];
        float h3 = hp[(size_t)(s0 + 3) * DD];
#pragma unroll
        for (int t = 0; t < TT; t++) {
            float4 a = *(const float4*)&ssc[t][s0];
            acc[t] += a.x * h0 + a.y * h1 + a.z * h2 + a.w * h3;
        }
    }
#pragma unroll
    for (int t = 0; t < TT; t++)
        g_ctx[((size_t)(b * TT + t)) * DD + d] = acc[t];
}

// ---------------------------------------------------------------------------
// Out projection: tokens[m,e] = ctx[m,:] . Wv_n[e,:] for head-n rows.
// grid 64 = n(4) x et(16, 32 cols); tile 128(M) x 32(N), 256 threads.
// ---------------------------------------------------------------------------
__global__ void __launch_bounds__(256) k_out(const float* __restrict__ Wv,
                                             float* __restrict__ out) {
    __shared__ float As[2][16][132];
    __shared__ float Bs[2][16][36];
    int tid = threadIdx.x;
    int n  = blockIdx.x >> 4;
    int e0 = (blockIdx.x & 15) * 32;

    int trow = tid >> 3;           // 0..31 -> rows trow*4
    int tcol = tid & 7;            // 0..7  -> cols tcol*4

    float acc[4][4];
#pragma unroll
    for (int i = 0; i < 4; i++)
#pragma unroll
        for (int j = 0; j < 4; j++) acc[i][j] = 0.0f;

    // loaders
    int arow0 = tid >> 2, akc = (tid & 3) * 4;        // +256 -> second half
    int brow = tid >> 2, bkc = (tid & 3) * 4;         // tid<128 only
    auto ctxrow = [&](int m) { return (m >> 1) * TT + n * 2 + (m & 1); };

    auto gload = [&](int s, float4* ra, float4* rb) {
        int k0 = s * 16;
        ra[0] = *(const float4*)(g_ctx + (size_t)ctxrow(arow0) * DD + k0 + akc);
        ra[1] = *(const float4*)(g_ctx + (size_t)ctxrow(arow0 + 64) * DD + k0 + akc);
        if (tid < 128)
            rb[0] = *(const float4*)(Wv + (size_t)(n * DD + e0 + brow) * DD + k0 + bkc);
    };
    auto sstore = [&](int buf, const float4* ra, const float4* rb) {
#pragma unroll
        for (int j = 0; j < 4; j++) {
            As[buf][akc + j][arow0]      = ((const float*)&ra[0])[j];
            As[buf][akc + j][arow0 + 64] = ((const float*)&ra[1])[j];
        }
        if (tid < 128)
#pragma unroll
            for (int j = 0; j < 4; j++)
                Bs[buf][bkc + j][brow] = ((const float*)&rb[0])[j];
    };

    float4 ra[2], rb[1];
    gload(0, ra, rb);
    sstore(0, ra, rb);
    __syncthreads();

    for (int s = 0; s < 32; s++) {
        int buf = s & 1;
        if (s + 1 < 32) gload(s + 1, ra, rb);
#pragma unroll
        for (int k = 0; k < 16; k++) {
            float arr[4], brr[4];
            *(float4*)arr = *(const float4*)&As[buf][k][trow * 4];
            *(float4*)brr = *(const float4*)&Bs[buf][k][tcol * 4];
#pragma unroll
            for (int i = 0; i < 4; i++)
#pragma unroll
                for (int j = 0; j < 4; j++) acc[i][j] += arr[i] * brr[j];
        }
        if (s + 1 < 32) {
            __syncthreads();
            sstore(buf ^ 1, ra, rb);
            __syncthreads();
        }
    }
#pragma unroll
    for (int i = 0; i < 4; i++) {
        int m = trow * 4 + i;
        *(float4*)&out[(size_t)ctxrow(m) * DD + e0 + tcol * 4] = *(float4*)acc[i];
    }
}

// ---------------------------------------------------------------------------
extern "C" void kernel_launch(void* const* d_in, const int* in_sizes, int n_in,
                              void* d_out, int out_size) {
    (void)in_sizes; (void)n_in; (void)out_size;
    const float* target = (const float*)d_in[0];
    const float* hist   = (const float*)d_in[1];
    const void*  mask   = d_in[2];
    const float* Wq     = (const float*)d_in[3];
    const float* Wk     = (const float*)d_in[4];
    const float* Wv     = (const float*)d_in[5];
    const float* qw     = (const float*)d_in[6];
    const float* kw     = (const float*)d_in[7];
    float* out = (float*)d_out;

    cudaFuncSetAttribute(k_knorm_fp16, cudaFuncAttributeMaxDynamicSharedMemorySize,
                         KN_SMEM);

    __half *hH, *wH;
    cudaGetSymbolAddress((void**)&hH, g_hH);
    cudaGetSymbolAddress((void**)&wH, g_wH);

    k_detect_mask<<<1, 256>>>((const unsigned int*)mask);
    k_tofp16<<<2048, 256>>>(hist, hH, BB * SS * DD / 4);
    k_tofp16<<<512, 256>>>(Wk, wH, NKVH * DD * DD / 4);
    k_qproj_gemm<<<64, 256>>>(target, Wq);
    k_qtilde<<<128, 512>>>(Wk, qw, kw);
    k_knorm_fp16<<<BB * NKVH * 4, 512, KN_SMEM>>>();
    k_attn2<<<BB, 512>>>(hist, mask, out);
    k_out<<<64, 256>>>(Wv, out);
}

// round 7
// speedup vs baseline: 4.0335x; 1.0953x over previous
#include <cuda_runtime.h>
#include <cuda_fp16.h>
#include <math.h>
#include <stdint.h>

// Problem constants
#define BB   64
#define TT   8
#define DD   512
#define SS   512
#define NKVH 4
#define QK_SCALE 0.044194173824159216f
#define EPS 1e-6f

// ---------------------------------------------------------------------------
// Device-global scratch
// ---------------------------------------------------------------------------
__device__ float g_q[BB * TT * DD];        // raw q projection
__device__ float g_qn[BB * TT * DD];       // normalized q * (1+qw)(1+kw)
__device__ float g_qt[BB * TT * DD];       // q-tilde
__device__ float g_sumsq[BB * NKVH * SS];
__device__ float g_ctx[BB * TT * DD];
__device__ int   g_mask_mode;
__device__ __half g_hH[BB * SS * DD];      // hist fp16
__device__ __half g_wH[NKVH * DD * DD];    // Wk fp16

// ---------------------------------------------------------------------------
// PTX helpers
// ---------------------------------------------------------------------------
__device__ __forceinline__ uint32_t smem_u32(const void* p) {
    uint32_t a;
    asm("{ .reg .u64 t; cvta.to.shared.u64 t, %1; cvt.u32.u64 %0, t; }"
        : "=r"(a) : "l"(p));
    return a;
}
__device__ __forceinline__ void cp_async16(uint32_t dst, const void* src) {
    asm volatile("cp.async.cg.shared.global [%0], [%1], 16;"
                 :: "r"(dst), "l"(src));
}
#define CPASYNC_COMMIT() asm volatile("cp.async.commit_group;" ::: "memory")
#define CPASYNC_WAIT1()  asm volatile("cp.async.wait_group 1;" ::: "memory")
#define CPASYNC_WAIT0()  asm volatile("cp.async.wait_group 0;" ::: "memory")

__device__ __forceinline__ void ldmatrix_x4(uint32_t& r0, uint32_t& r1,
                                            uint32_t& r2, uint32_t& r3,
                                            uint32_t addr) {
    asm volatile("ldmatrix.sync.aligned.m8n8.x4.shared.b16 {%0,%1,%2,%3}, [%4];"
                 : "=r"(r0), "=r"(r1), "=r"(r2), "=r"(r3) : "r"(addr));
}
__device__ __forceinline__ void mma_fp16(float* d, const uint32_t* a,
                                         const uint32_t* b) {
    asm volatile(
        "mma.sync.aligned.m16n8k16.row.col.f32.f16.f16.f32 "
        "{%0,%1,%2,%3}, {%4,%5,%6,%7}, {%8,%9}, {%0,%1,%2,%3};"
        : "+f"(d[0]), "+f"(d[1]), "+f"(d[2]), "+f"(d[3])
        : "r"(a[0]), "r"(a[1]), "r"(a[2]), "r"(a[3]), "r"(b[0]), "r"(b[1]));
}

// ---------------------------------------------------------------------------
// Mask dtype sniffer
// ---------------------------------------------------------------------------
__global__ void k_detect_mask(const unsigned int* __restrict__ m) {
    __shared__ int flags[3];
    int tid = threadIdx.x;
    if (tid < 3) flags[tid] = 1;
    __syncthreads();
    int iok = 1, fok = 1, hok = 1;
    for (int i = tid; i < 8192; i += blockDim.x) {
        unsigned w = m[i];
        if (w > 1u) iok = 0;
        float f = __uint_as_float(w);
        if (!(f == 0.0f || f == 1.0f)) fok = 0;
        unsigned lo = w & 0xFFFFu, hi = w >> 16;
        if (!((lo == 0u || lo == 0x3F80u) && (hi == 0u || hi == 0x3F80u))) hok = 0;
    }
    if (!iok) atomicExch(&flags[0], 0);
    if (!fok) atomicExch(&flags[1], 0);
    if (!hok) atomicExch(&flags[2], 0);
    __syncthreads();
    if (tid == 0)
        g_mask_mode = flags[0] ? 0 : (flags[1] ? 1 : (flags[2] ? 3 : 2));
}
__device__ __forceinline__ bool is_masked(const void* m, int idx, int mode) {
    if (mode == 0) return ((const int*)m)[idx] != 0;
    if (mode == 1) return ((const float*)m)[idx] != 0.0f;
    if (mode == 3) return ((const unsigned short*)m)[idx] != 0;
    return ((const unsigned char*)m)[idx] != 0;
}

// ---------------------------------------------------------------------------
// fp32 -> fp16 conversion
// ---------------------------------------------------------------------------
__global__ void k_tofp16(const float* __restrict__ src,
                         __half* __restrict__ dst, int n4) {
    int i = blockIdx.x * blockDim.x + threadIdx.x;
    int stride = gridDim.x * blockDim.x;
    for (; i < n4; i += stride) {
        float4 v = ((const float4*)src)[i];
        ((__half2*)dst)[i * 2 + 0] = __floats2half2_rn(v.x, v.y);
        ((__half2*)dst)[i * 2 + 1] = __floats2half2_rn(v.z, v.w);
    }
}

// ---------------------------------------------------------------------------
// Raw Q projection: coalesced tiled SGEMM, 64x64 tiles, double-buffered.
// ---------------------------------------------------------------------------
__global__ void __launch_bounds__(256) k_qproj_gemm(const float* __restrict__ tgt,
                                                    const float* __restrict__ Wq) {
    __shared__ float As[2][16][68];
    __shared__ float Bs[2][16][68];
    int tid = threadIdx.x;
    int m0 = (blockIdx.x >> 3) * 64;
    int e0 = (blockIdx.x & 7) * 64;

    int lrow = tid >> 2;
    int lkc  = (tid & 3) * 4;
    int trow = tid >> 4;
    int tcol = tid & 15;

    float acc[4][4];
#pragma unroll
    for (int i = 0; i < 4; i++)
#pragma unroll
        for (int j = 0; j < 4; j++) acc[i][j] = 0.0f;

    float4 ra = *(const float4*)(tgt + (size_t)(m0 + lrow) * DD + lkc);
    float4 rb = *(const float4*)(Wq  + (size_t)(e0 + lrow) * DD + lkc);
#pragma unroll
    for (int j = 0; j < 4; j++) {
        As[0][lkc + j][lrow] = ((const float*)&ra)[j];
        Bs[0][lkc + j][lrow] = ((const float*)&rb)[j];
    }
    __syncthreads();

    for (int s = 0; s < 32; s++) {
        int buf = s & 1;
        if (s + 1 < 32) {
            int k0 = (s + 1) * 16;
            ra = *(const float4*)(tgt + (size_t)(m0 + lrow) * DD + k0 + lkc);
            rb = *(const float4*)(Wq  + (size_t)(e0 + lrow) * DD + k0 + lkc);
        }
#pragma unroll
        for (int k = 0; k < 16; k++) {
            float ar[4], br[4];
            *(float4*)ar = *(const float4*)&As[buf][k][trow * 4];
            *(float4*)br = *(const float4*)&Bs[buf][k][tcol * 4];
#pragma unroll
            for (int i = 0; i < 4; i++)
#pragma unroll
                for (int j = 0; j < 4; j++) acc[i][j] += ar[i] * br[j];
        }
        if (s + 1 < 32) {
            __syncthreads();
#pragma unroll
            for (int j = 0; j < 4; j++) {
                As[buf ^ 1][lkc + j][lrow] = ((const float*)&ra)[j];
                Bs[buf ^ 1][lkc + j][lrow] = ((const float*)&rb)[j];
            }
            __syncthreads();
        }
    }
#pragma unroll
    for (int i = 0; i < 4; i++)
        *(float4*)&g_q[(size_t)(m0 + trow * 4 + i) * DD + e0 + tcol * 4] =
            *(float4*)acc[i];
}

// ---------------------------------------------------------------------------
// Q RMS-norm: one warp per row; qn = q*inv_rms*(1+qw)*(1+kw)
// grid 64 x 256 thr (8 warps = 8 rows)
// ---------------------------------------------------------------------------
__global__ void __launch_bounds__(256) k_qnorm(const float* __restrict__ qw,
                                               const float* __restrict__ kw) {
    int wid = threadIdx.x >> 5, lane = threadIdx.x & 31;
    int row = blockIdx.x * 8 + wid;
    const float4* src = (const float4*)(g_q + (size_t)row * DD);
    float4 v[4];
    float ss = 0.0f;
#pragma unroll
    for (int j = 0; j < 4; j++) {
        v[j] = src[lane + 32 * j];
        ss += v[j].x * v[j].x + v[j].y * v[j].y + v[j].z * v[j].z + v[j].w * v[j].w;
    }
#pragma unroll
    for (int off = 16; off > 0; off >>= 1)
        ss += __shfl_xor_sync(0xFFFFFFFFu, ss, off);
    float inv = rsqrtf(ss * (1.0f / (float)DD) + EPS);
    float4* dst = (float4*)(g_qn + (size_t)row * DD);
#pragma unroll
    for (int j = 0; j < 4; j++) {
        int e4 = (lane + 32 * j) * 4;
        float4 wq = *(const float4*)(qw + e4);
        float4 wk = *(const float4*)(kw + e4);
        float4 o;
        o.x = v[j].x * inv * (1.0f + wq.x) * (1.0f + wk.x);
        o.y = v[j].y * inv * (1.0f + wq.y) * (1.0f + wk.y);
        o.z = v[j].z * inv * (1.0f + wq.z) * (1.0f + wk.z);
        o.w = v[j].w * inv * (1.0f + wq.w) * (1.0f + wk.w);
        dst[lane + 32 * j] = o;
    }
}

// ---------------------------------------------------------------------------
// q-tilde GEMM: qt[m,d] = sum_e qn[m,e] * Wk[n*D+e, d] * SCALE
// grid 64 = n(4) x mt(2) x nt(8); tiles 64(M) x 64(N), K=512, double-buffered.
// M-rows of head n: m -> (b = m>>1, t = n*2 + (m&1))
// ---------------------------------------------------------------------------
__global__ void __launch_bounds__(256) k_qtilde_gemm(const float* __restrict__ Wk) {
    __shared__ float As[2][16][68];
    __shared__ float Bs[2][16][68];
    int tid = threadIdx.x;
    int n  = blockIdx.x >> 4;
    int mt = (blockIdx.x >> 3) & 1;
    int nt = blockIdx.x & 7;
    int m0 = mt * 64;
    int d0 = nt * 64;

    auto grow = [&](int m) { return (m >> 1) * TT + n * 2 + (m & 1); };

    int lrow = tid >> 2;            // A: 0..63 tile row
    int lkc  = (tid & 3) * 4;
    int bkr  = tid >> 4;            // B: 0..15 k-row
    int bnn  = (tid & 3) * 4;       // unused; use full mapping below
    int bn4  = (tid & 15) * 4;      // B cols
    int trow = tid >> 4;
    int tcol = tid & 15;

    size_t arow_off = (size_t)grow(m0 + lrow) * DD;
    const float* wbase = Wk + (size_t)n * DD * DD + d0;

    float acc[4][4];
#pragma unroll
    for (int i = 0; i < 4; i++)
#pragma unroll
        for (int j = 0; j < 4; j++) acc[i][j] = 0.0f;

    float4 ra = *(const float4*)(g_qn + arow_off + lkc);
    float4 rb = *(const float4*)(wbase + (size_t)bkr * DD + bn4);
#pragma unroll
    for (int j = 0; j < 4; j++) As[0][lkc + j][lrow] = ((const float*)&ra)[j];
    *(float4*)&Bs[0][bkr][bn4] = rb;
    __syncthreads();

    for (int s = 0; s < 32; s++) {
        int buf = s & 1;
        if (s + 1 < 32) {
            int k0 = (s + 1) * 16;
            ra = *(const float4*)(g_qn + arow_off + k0 + lkc);
            rb = *(const float4*)(wbase + (size_t)(k0 + bkr) * DD + bn4);
        }
#pragma unroll
        for (int k = 0; k < 16; k++) {
            float ar[4], br[4];
            *(float4*)ar = *(const float4*)&As[buf][k][trow * 4];
            *(float4*)br = *(const float4*)&Bs[buf][k][tcol * 4];
#pragma unroll
            for (int i = 0; i < 4; i++)
#pragma unroll
                for (int j = 0; j < 4; j++) acc[i][j] += ar[i] * br[j];
        }
        if (s + 1 < 32) {
            __syncthreads();
#pragma unroll
            for (int j = 0; j < 4; j++) As[buf ^ 1][lkc + j][lrow] = ((const float*)&ra)[j];
            *(float4*)&Bs[buf ^ 1][bkr][bn4] = rb;
            __syncthreads();
        }
    }
#pragma unroll
    for (int i = 0; i < 4; i++) {
        float4 o;
        o.x = acc[i][0] * QK_SCALE; o.y = acc[i][1] * QK_SCALE;
        o.z = acc[i][2] * QK_SCALE; o.w = acc[i][3] * QK_SCALE;
        *(float4*)&g_qt[(size_t)grow(m0 + trow * 4 + i) * DD + d0 + tcol * 4] = o;
    }
}

// ---------------------------------------------------------------------------
__global__ void k_zero_sumsq() {
    int i = blockIdx.x * blockDim.x + threadIdx.x;
    if (i < BB * NKVH * SS) g_sumsq[i] = 0.0f;
}

// ---------------------------------------------------------------------------
// fp16 HMMA norm GEMM, R3 structure: CTA 128x128, 256 thr (8 warps 4Mx2N,
// warp tile 32x64), Kc=32, 3-slot cp.async, 61KB smem -> 2 CTAs/SM.
// grid 4096 = b(64) x n(4) x stile(4) x etile(4).
// ---------------------------------------------------------------------------
#define KN_ROWB   80
#define KN_ATILE  (128 * KN_ROWB)            // 10240
#define KN_STAGE  (2 * KN_ATILE)             // 20480
#define KN_SMEM   (3 * KN_STAGE)             // 61440
#define KN_NSTAGE 16                         // 512 / 32

__global__ void __launch_bounds__(256) k_knorm_fp16() {
    extern __shared__ __align__(16) char smem[];
    uint32_t sbase = smem_u32(smem);

    int tid = threadIdx.x;
    int wid = tid >> 5, lane = tid & 31;
    int warp_m = wid & 3;
    int warp_n = wid >> 2;

    int bx = blockIdx.x;
    int etile = bx & 3;
    int stile = (bx >> 2) & 3;
    int n = (bx >> 4) & 3;
    int b = bx >> 6;
    int s0 = stile * 128;
    int e0 = etile * 128;

    const __half* Abase = g_hH + (size_t)b * SS * DD;
    const __half* Bbase = g_wH + (size_t)n * DD * DD;

    int lrow = tid >> 1;
    int lhalf = tid & 1;
    size_t a_goff = (size_t)(s0 + lrow) * DD + lhalf * 16;
    size_t b_goff = (size_t)(e0 + lrow) * DD + lhalf * 16;
    uint32_t s_loff = (uint32_t)(lrow * KN_ROWB + lhalf * 32);

    int g = lane >> 3, lr = lane & 7;
    int a_row16 = ((g & 1) << 3) + lr;
    int a_kc = g >> 1;
    uint32_t a_off0 = (uint32_t)((warp_m * 32 + a_row16) * KN_ROWB + a_kc * 16);
    uint32_t a_off1 = a_off0 + 16 * KN_ROWB;
    int b_row16 = ((g >> 1) << 3) + lr;
    int b_kc = g & 1;
    uint32_t b_off[4];
#pragma unroll
    for (int p = 0; p < 4; p++)
        b_off[p] = (uint32_t)(KN_ATILE +
                   (warp_n * 64 + p * 16 + b_row16) * KN_ROWB + b_kc * 16);

    float acc[2][8][4];
#pragma unroll
    for (int mt = 0; mt < 2; mt++)
#pragma unroll
        for (int nt = 0; nt < 8; nt++)
#pragma unroll
            for (int c = 0; c < 4; c++) acc[mt][nt][c] = 0.0f;

    auto load_stage = [&](int kt) {
        int k0 = kt * 32;
        uint32_t sb = sbase + (uint32_t)(kt % 3) * KN_STAGE;
        const __half* as = Abase + a_goff + k0;
        const __half* bs = Bbase + b_goff + k0;
        cp_async16(sb + s_loff, as);
        cp_async16(sb + s_loff + 16, as + 8);
        cp_async16(sb + KN_ATILE + s_loff, bs);
        cp_async16(sb + KN_ATILE + s_loff + 16, bs + 8);
        CPASYNC_COMMIT();
    };

    load_stage(0);
    load_stage(1);

    for (int i = 0; i < KN_NSTAGE; i++) {
        if (i == KN_NSTAGE - 1) { CPASYNC_WAIT0(); } else { CPASYNC_WAIT1(); }
        __syncthreads();
        if (i + 2 < KN_NSTAGE) load_stage(i + 2);

        uint32_t sb = sbase + (uint32_t)(i % 3) * KN_STAGE;
#pragma unroll
        for (int ks = 0; ks < 2; ks++) {
            uint32_t koff = (uint32_t)(ks * 32);
            uint32_t afrag[2][4];
            uint32_t bfrag[8][2];
            ldmatrix_x4(afrag[0][0], afrag[0][1], afrag[0][2], afrag[0][3],
                        sb + a_off0 + koff);
            ldmatrix_x4(afrag[1][0], afrag[1][1], afrag[1][2], afrag[1][3],
                        sb + a_off1 + koff);
#pragma unroll
            for (int p = 0; p < 4; p++) {
                ldmatrix_x4(bfrag[2 * p][0], bfrag[2 * p][1],
                            bfrag[2 * p + 1][0], bfrag[2 * p + 1][1],
                            sb + b_off[p] + koff);
            }
#pragma unroll
            for (int mt = 0; mt < 2; mt++)
#pragma unroll
                for (int nt = 0; nt < 8; nt++)
                    mma_fp16(acc[mt][nt], afrag[mt], bfrag[nt]);
        }
    }

    // epilogue: square, quad-reduce, atomicAdd per row
    size_t sbidx = ((size_t)(b * NKVH + n)) * SS + s0;
#pragma unroll
    for (int mt = 0; mt < 2; mt++) {
        float slo = 0.0f, shi = 0.0f;
#pragma unroll
        for (int nt = 0; nt < 8; nt++) {
            slo += acc[mt][nt][0] * acc[mt][nt][0] + acc[mt][nt][1] * acc[mt][nt][1];
            shi += acc[mt][nt][2] * acc[mt][nt][2] + acc[mt][nt][3] * acc[mt][nt][3];
        }
        slo += __shfl_xor_sync(0xFFFFFFFFu, slo, 1);
        slo += __shfl_xor_sync(0xFFFFFFFFu, slo, 2);
        shi += __shfl_xor_sync(0xFFFFFFFFu, shi, 1);
        shi += __shfl_xor_sync(0xFFFFFFFFu, shi, 2);
        if ((lane & 3) == 0) {
            int row = warp_m * 32 + mt * 16 + (lane >> 2);
            atomicAdd(&g_sumsq[sbidx + row], slo);
            atomicAdd(&g_sumsq[sbidx + row + 8], shi);
        }
    }
}

// ---------------------------------------------------------------------------
// Attention (scores + softmax + ctx), all heads per block. grid 64, 512 thr.
// ---------------------------------------------------------------------------
__global__ void __launch_bounds__(512) k_attn2(const float* __restrict__ hist,
                                               const void*  __restrict__ mask,
                                               float* __restrict__ out) {
    int b = blockIdx.x;
    int tid = threadIdx.x;
    int wid = tid >> 5, lane = tid & 31;
    int mode = g_mask_mode;

    __shared__ float sqt[TT][DD];
    __shared__ float ssc[TT][SS];

    for (int i = tid; i < TT * DD; i += 512)
        sqt[i >> 9][i & 511] = g_qt[(size_t)(b * TT) * DD + i];
    __syncthreads();

    for (int r = 0; r < 32; r++) {
        int s = wid * 32 + r;
        const float4* hp = (const float4*)(hist + ((size_t)(b * SS + s)) * DD);
        float4 h[4];
#pragma unroll
        for (int i = 0; i < 4; i++) h[i] = hp[lane + 32 * i];
        float p[TT];
#pragma unroll
        for (int t = 0; t < TT; t++) {
            const float4* q4 = (const float4*)sqt[t];
            float a = 0.0f;
#pragma unroll
            for (int i = 0; i < 4; i++) {
                float4 q = q4[lane + 32 * i];
                a += q.x * h[i].x + q.y * h[i].y + q.z * h[i].z + q.w * h[i].w;
            }
            p[t] = a;
        }
#pragma unroll
        for (int off = 16; off > 0; off >>= 1)
#pragma unroll
            for (int t = 0; t < TT; t++)
                p[t] += __shfl_xor_sync(0xFFFFFFFFu, p[t], off);
        if (lane == 0) {
            bool mk = is_masked(mask, b * SS + s, mode);
#pragma unroll
            for (int n = 0; n < NKVH; n++) {
                float inv = rsqrtf(g_sumsq[((size_t)(b * NKVH + n)) * SS + s]
                                   * (1.0f / (float)DD) + EPS);
                ssc[n * 2][s]     = mk ? -INFINITY : p[n * 2] * inv;
                ssc[n * 2 + 1][s] = mk ? -INFINITY : p[n * 2 + 1] * inv;
            }
        }
    }
    __syncthreads();

    if (wid < TT) {
        int t = wid;
        float v[16];
        float mx = -INFINITY;
#pragma unroll
        for (int j = 0; j < 16; j++) {
            v[j] = ssc[t][lane + 32 * j];
            mx = fmaxf(mx, v[j]);
        }
#pragma unroll
        for (int off = 16; off > 0; off >>= 1)
            mx = fmaxf(mx, __shfl_xor_sync(0xFFFFFFFFu, mx, off));
        float sum = 0.0f;
#pragma unroll
        for (int j = 0; j < 16; j++) { v[j] = expf(v[j] - mx); sum += v[j]; }
#pragma unroll
        for (int off = 16; off > 0; off >>= 1)
            sum += __shfl_xor_sync(0xFFFFFFFFu, sum, off);
        float is = 1.0f / sum;
        size_t wbase = (size_t)BB * TT * DD + ((size_t)(b * TT + t)) * SS;
#pragma unroll
        for (int j = 0; j < 16; j++) {
            float a = v[j] * is;
            ssc[t][lane + 32 * j] = a;
            out[wbase + lane + 32 * j] = a;
        }
    }
    __syncthreads();

    int d = tid;
    float acc[TT];
#pragma unroll
    for (int t = 0; t < TT; t++) acc[t] = 0.0f;
    const float* hp = hist + (size_t)b * SS * DD + d;
    for (int s0 = 0; s0 < SS; s0 += 4) {
        float h0 = hp[(size_t)s0 * DD];
        float h1 = hp[(size_t)(s0 + 1) * DD];
        float h2 = hp[(size_t)(s0 + 2) * DD];
        float h3 = hp[(size_t)(s0 + 3) * DD];
#pragma unroll
        for (int t = 0; t < TT; t++) {
            float4 a = *(const float4*)&ssc[t][s0];
            acc[t] += a.x * h0 + a.y * h1 + a.z * h2 + a.w * h3;
        }
    }
#pragma unroll
    for (int t = 0; t < TT; t++)
        g_ctx[((size_t)(b * TT + t)) * DD + d] = acc[t];
}

// ---------------------------------------------------------------------------
// Out projection: tokens[m,e] = ctx[m,:] . Wv_n[e,:].
// grid 64 = n(4) x et(16); tile 128(M) x 32(N), 256 threads.
// ---------------------------------------------------------------------------
__global__ void __launch_bounds__(256) k_out(const float* __restrict__ Wv,
                                             float* __restrict__ out) {
    __shared__ float As[2][16][132];
    __shared__ float Bs[2][16][36];
    int tid = threadIdx.x;
    int n  = blockIdx.x >> 4;
    int e0 = (blockIdx.x & 15) * 32;

    int trow = tid >> 3;
    int tcol = tid & 7;

    float acc[4][4];
#pragma unroll
    for (int i = 0; i < 4; i++)
#pragma unroll
        for (int j = 0; j < 4; j++) acc[i][j] = 0.0f;

    int arow0 = tid >> 2, akc = (tid & 3) * 4;
    int brow = tid >> 2, bkc = (tid & 3) * 4;
    auto ctxrow = [&](int m) { return (m >> 1) * TT + n * 2 + (m & 1); };

    auto gload = [&](int s, float4* ra, float4* rb) {
        int k0 = s * 16;
        ra[0] = *(const float4*)(g_ctx + (size_t)ctxrow(arow0) * DD + k0 + akc);
        ra[1] = *(const float4*)(g_ctx + (size_t)ctxrow(arow0 + 64) * DD + k0 + akc);
        if (tid < 128)
            rb[0] = *(const float4*)(Wv + (size_t)(n * DD + e0 + brow) * DD + k0 + bkc);
    };
    auto sstore = [&](int buf, const float4* ra, const float4* rb) {
#pragma unroll
        for (int j = 0; j < 4; j++) {
            As[buf][akc + j][arow0]      = ((const float*)&ra[0])[j];
            As[buf][akc + j][arow0 + 64] = ((const float*)&ra[1])[j];
        }
        if (tid < 128)
#pragma unroll
            for (int j = 0; j < 4; j++)
                Bs[buf][bkc + j][brow] = ((const float*)&rb[0])[j];
    };

    float4 ra[2], rb[1];
    gload(0, ra, rb);
    sstore(0, ra, rb);
    __syncthreads();

    for (int s = 0; s < 32; s++) {
        int buf = s & 1;
        if (s + 1 < 32) gload(s + 1, ra, rb);
#pragma unroll
        for (int k = 0; k < 16; k++) {
            float arr[4], brr[4];
            *(float4*)arr = *(const float4*)&As[buf][k][trow * 4];
            *(float4*)brr = *(const float4*)&Bs[buf][k][tcol * 4];
#pragma unroll
            for (int i = 0; i < 4; i++)
#pragma unroll
                for (int j = 0; j < 4; j++) acc[i][j] += arr[i] * brr[j];
        }
        if (s + 1 < 32) {
            __syncthreads();
            sstore(buf ^ 1, ra, rb);
            __syncthreads();
        }
    }
#pragma unroll
    for (int i = 0; i < 4; i++) {
        int m = trow * 4 + i;
        *(float4*)&out[(size_t)ctxrow(m) * DD + e0 + tcol * 4] = *(float4*)acc[i];
    }
}

// ---------------------------------------------------------------------------
extern "C" void kernel_launch(void* const* d_in, const int* in_sizes, int n_in,
                              void* d_out, int out_size) {
    (void)in_sizes; (void)n_in; (void)out_size;
    const float* target = (const float*)d_in[0];
    const float* hist   = (const float*)d_in[1];
    const void*  mask   = d_in[2];
    const float* Wq     = (const float*)d_in[3];
    const float* Wk     = (const float*)d_in[4];
    const float* Wv     = (const float*)d_in[5];
    const float* qw     = (const float*)d_in[6];
    const float* kw     = (const float*)d_in[7];
    float* out = (float*)d_out;

    cudaFuncSetAttribute(k_knorm_fp16, cudaFuncAttributeMaxDynamicSharedMemorySize,
                         KN_SMEM);

    __half *hH, *wH;
    cudaGetSymbolAddress((void**)&hH, g_hH);
    cudaGetSymbolAddress((void**)&wH, g_wH);

    k_detect_mask<<<1, 256>>>((const unsigned int*)mask);
    k_tofp16<<<2048, 256>>>(hist, hH, BB * SS * DD / 4);
    k_tofp16<<<512, 256>>>(Wk, wH, NKVH * DD * DD / 4);
    k_qproj_gemm<<<64, 256>>>(target, Wq);
    k_qnorm<<<64, 256>>>(qw, kw);
    k_qtilde_gemm<<<64, 256>>>(Wk);
    k_zero_sumsq<<<512, 256>>>();
    k_knorm_fp16<<<BB * NKVH * 16, 256, KN_SMEM>>>();
    k_attn2<<<BB, 512>>>(hist, mask, out);
    k_out<<<64, 256>>>(Wv, out);
}

// round 8
// speedup vs baseline: 4.1410x; 1.0267x over previous
#include <cuda_runtime.h>
#include <cuda_fp16.h>
#include <math.h>
#include <stdint.h>

// Problem constants
#define BB   64
#define TT   8
#define DD   512
#define SS   512
#define NKVH 4
#define QK_SCALE 0.044194173824159216f
#define EPS 1e-6f

// ---------------------------------------------------------------------------
// Device-global scratch
// ---------------------------------------------------------------------------
__device__ float g_q[BB * TT * DD];         // raw q projection
__device__ float g_qn[BB * TT * DD];        // normalized q * (1+qw)(1+kw)
__device__ float g_qt[BB * TT * DD];        // q-tilde
__device__ float g_sumsq[BB * NKVH * SS];
__device__ float g_sc[BB * TT * SS];        // scores, then attn
__device__ float g_ctxp[4][BB * TT * DD];   // ctx partials per stile
__device__ int   g_mask_mode;
__device__ __half g_hH[BB * SS * DD];       // hist fp16
__device__ __half g_wH[NKVH * DD * DD];     // Wk fp16

// ---------------------------------------------------------------------------
// PTX helpers
// ---------------------------------------------------------------------------
__device__ __forceinline__ uint32_t smem_u32(const void* p) {
    uint32_t a;
    asm("{ .reg .u64 t; cvta.to.shared.u64 t, %1; cvt.u32.u64 %0, t; }"
        : "=r"(a) : "l"(p));
    return a;
}
__device__ __forceinline__ void cp_async16(uint32_t dst, const void* src) {
    asm volatile("cp.async.cg.shared.global [%0], [%1], 16;"
                 :: "r"(dst), "l"(src));
}
#define CPASYNC_COMMIT() asm volatile("cp.async.commit_group;" ::: "memory")
#define CPASYNC_WAIT2()  asm volatile("cp.async.wait_group 2;" ::: "memory")
#define CPASYNC_WAIT1()  asm volatile("cp.async.wait_group 1;" ::: "memory")
#define CPASYNC_WAIT0()  asm volatile("cp.async.wait_group 0;" ::: "memory")

__device__ __forceinline__ void ldmatrix_x4(uint32_t& r0, uint32_t& r1,
                                            uint32_t& r2, uint32_t& r3,
                                            uint32_t addr) {
    asm volatile("ldmatrix.sync.aligned.m8n8.x4.shared.b16 {%0,%1,%2,%3}, [%4];"
                 : "=r"(r0), "=r"(r1), "=r"(r2), "=r"(r3) : "r"(addr));
}
__device__ __forceinline__ void mma_fp16(float* d, const uint32_t* a,
                                         const uint32_t* b) {
    asm volatile(
        "mma.sync.aligned.m16n8k16.row.col.f32.f16.f16.f32 "
        "{%0,%1,%2,%3}, {%4,%5,%6,%7}, {%8,%9}, {%0,%1,%2,%3};"
        : "+f"(d[0]), "+f"(d[1]), "+f"(d[2]), "+f"(d[3])
        : "r"(a[0]), "r"(a[1]), "r"(a[2]), "r"(a[3]), "r"(b[0]), "r"(b[1]));
}

// ---------------------------------------------------------------------------
// Mask dtype sniffer
// ---------------------------------------------------------------------------
__global__ void k_detect_mask(const unsigned int* __restrict__ m) {
    __shared__ int flags[3];
    int tid = threadIdx.x;
    if (tid < 3) flags[tid] = 1;
    __syncthreads();
    int iok = 1, fok = 1, hok = 1;
    for (int i = tid; i < 8192; i += blockDim.x) {
        unsigned w = m[i];
        if (w > 1u) iok = 0;
        float f = __uint_as_float(w);
        if (!(f == 0.0f || f == 1.0f)) fok = 0;
        unsigned lo = w & 0xFFFFu, hi = w >> 16;
        if (!((lo == 0u || lo == 0x3F80u) && (hi == 0u || hi == 0x3F80u))) hok = 0;
    }
    if (!iok) atomicExch(&flags[0], 0);
    if (!fok) atomicExch(&flags[1], 0);
    if (!hok) atomicExch(&flags[2], 0);
    __syncthreads();
    if (tid == 0)
        g_mask_mode = flags[0] ? 0 : (flags[1] ? 1 : (flags[2] ? 3 : 2));
}
__device__ __forceinline__ bool is_masked(const void* m, int idx, int mode) {
    if (mode == 0) return ((const int*)m)[idx] != 0;
    if (mode == 1) return ((const float*)m)[idx] != 0.0f;
    if (mode == 3) return ((const unsigned short*)m)[idx] != 0;
    return ((const unsigned char*)m)[idx] != 0;
}

// ---------------------------------------------------------------------------
// fp32 -> fp16 conversion
// ---------------------------------------------------------------------------
__global__ void k_tofp16(const float* __restrict__ src,
                         __half* __restrict__ dst, int n4) {
    int i = blockIdx.x * blockDim.x + threadIdx.x;
    int stride = gridDim.x * blockDim.x;
    for (; i < n4; i += stride) {
        float4 v = ((const float4*)src)[i];
        ((__half2*)dst)[i * 2 + 0] = __floats2half2_rn(v.x, v.y);
        ((__half2*)dst)[i * 2 + 1] = __floats2half2_rn(v.z, v.w);
    }
}

// ---------------------------------------------------------------------------
// Raw Q projection: coalesced tiled SGEMM, 64x64 tiles, double-buffered.
// ---------------------------------------------------------------------------
__global__ void __launch_bounds__(256) k_qproj_gemm(const float* __restrict__ tgt,
                                                    const float* __restrict__ Wq) {
    __shared__ float As[2][16][68];
    __shared__ float Bs[2][16][68];
    int tid = threadIdx.x;
    int m0 = (blockIdx.x >> 3) * 64;
    int e0 = (blockIdx.x & 7) * 64;

    int lrow = tid >> 2;
    int lkc  = (tid & 3) * 4;
    int trow = tid >> 4;
    int tcol = tid & 15;

    float acc[4][4];
#pragma unroll
    for (int i = 0; i < 4; i++)
#pragma unroll
        for (int j = 0; j < 4; j++) acc[i][j] = 0.0f;

    float4 ra = *(const float4*)(tgt + (size_t)(m0 + lrow) * DD + lkc);
    float4 rb = *(const float4*)(Wq  + (size_t)(e0 + lrow) * DD + lkc);
#pragma unroll
    for (int j = 0; j < 4; j++) {
        As[0][lkc + j][lrow] = ((const float*)&ra)[j];
        Bs[0][lkc + j][lrow] = ((const float*)&rb)[j];
    }
    __syncthreads();

    for (int s = 0; s < 32; s++) {
        int buf = s & 1;
        if (s + 1 < 32) {
            int k0 = (s + 1) * 16;
            ra = *(const float4*)(tgt + (size_t)(m0 + lrow) * DD + k0 + lkc);
            rb = *(const float4*)(Wq  + (size_t)(e0 + lrow) * DD + k0 + lkc);
        }
#pragma unroll
        for (int k = 0; k < 16; k++) {
            float ar[4], br[4];
            *(float4*)ar = *(const float4*)&As[buf][k][trow * 4];
            *(float4*)br = *(const float4*)&Bs[buf][k][tcol * 4];
#pragma unroll
            for (int i = 0; i < 4; i++)
#pragma unroll
                for (int j = 0; j < 4; j++) acc[i][j] += ar[i] * br[j];
        }
        if (s + 1 < 32) {
            __syncthreads();
#pragma unroll
            for (int j = 0; j < 4; j++) {
                As[buf ^ 1][lkc + j][lrow] = ((const float*)&ra)[j];
                Bs[buf ^ 1][lkc + j][lrow] = ((const float*)&rb)[j];
            }
            __syncthreads();
        }
    }
#pragma unroll
    for (int i = 0; i < 4; i++)
        *(float4*)&g_q[(size_t)(m0 + trow * 4 + i) * DD + e0 + tcol * 4] =
            *(float4*)acc[i];
}

// ---------------------------------------------------------------------------
// Q RMS-norm: one warp per row; qn = q*inv_rms*(1+qw)*(1+kw)
// ---------------------------------------------------------------------------
__global__ void __launch_bounds__(256) k_qnorm(const float* __restrict__ qw,
                                               const float* __restrict__ kw) {
    int wid = threadIdx.x >> 5, lane = threadIdx.x & 31;
    int row = blockIdx.x * 8 + wid;
    const float4* src = (const float4*)(g_q + (size_t)row * DD);
    float4 v[4];
    float ss = 0.0f;
#pragma unroll
    for (int j = 0; j < 4; j++) {
        v[j] = src[lane + 32 * j];
        ss += v[j].x * v[j].x + v[j].y * v[j].y + v[j].z * v[j].z + v[j].w * v[j].w;
    }
#pragma unroll
    for (int off = 16; off > 0; off >>= 1)
        ss += __shfl_xor_sync(0xFFFFFFFFu, ss, off);
    float inv = rsqrtf(ss * (1.0f / (float)DD) + EPS);
    float4* dst = (float4*)(g_qn + (size_t)row * DD);
#pragma unroll
    for (int j = 0; j < 4; j++) {
        int e4 = (lane + 32 * j) * 4;
        float4 wq = *(const float4*)(qw + e4);
        float4 wk = *(const float4*)(kw + e4);
        float4 o;
        o.x = v[j].x * inv * (1.0f + wq.x) * (1.0f + wk.x);
        o.y = v[j].y * inv * (1.0f + wq.y) * (1.0f + wk.y);
        o.z = v[j].z * inv * (1.0f + wq.z) * (1.0f + wk.z);
        o.w = v[j].w * inv * (1.0f + wq.w) * (1.0f + wk.w);
        dst[lane + 32 * j] = o;
    }
}

// ---------------------------------------------------------------------------
// q-tilde GEMM: qt[m,d] = sum_e qn[m,e] * Wk[n*D+e, d] * SCALE
// grid 64 = n(4) x mt(2) x nt(8); 64x64 tiles, double-buffered.
// ---------------------------------------------------------------------------
__global__ void __launch_bounds__(256) k_qtilde_gemm(const float* __restrict__ Wk) {
    __shared__ float As[2][16][68];
    __shared__ float Bs[2][16][68];
    int tid = threadIdx.x;
    int n  = blockIdx.x >> 4;
    int mt = (blockIdx.x >> 3) & 1;
    int nt = blockIdx.x & 7;
    int m0 = mt * 64;
    int d0 = nt * 64;

    auto grow = [&](int m) { return (m >> 1) * TT + n * 2 + (m & 1); };

    int lrow = tid >> 2;
    int lkc  = (tid & 3) * 4;
    int bkr  = tid >> 4;
    int bn4  = (tid & 15) * 4;
    int trow = tid >> 4;
    int tcol = tid & 15;

    size_t arow_off = (size_t)grow(m0 + lrow) * DD;
    const float* wbase = Wk + (size_t)n * DD * DD + d0;

    float acc[4][4];
#pragma unroll
    for (int i = 0; i < 4; i++)
#pragma unroll
        for (int j = 0; j < 4; j++) acc[i][j] = 0.0f;

    float4 ra = *(const float4*)(g_qn + arow_off + lkc);
    float4 rb = *(const float4*)(wbase + (size_t)bkr * DD + bn4);
#pragma unroll
    for (int j = 0; j < 4; j++) As[0][lkc + j][lrow] = ((const float*)&ra)[j];
    *(float4*)&Bs[0][bkr][bn4] = rb;
    __syncthreads();

    for (int s = 0; s < 32; s++) {
        int buf = s & 1;
        if (s + 1 < 32) {
            int k0 = (s + 1) * 16;
            ra = *(const float4*)(g_qn + arow_off + k0 + lkc);
            rb = *(const float4*)(wbase + (size_t)(k0 + bkr) * DD + bn4);
        }
#pragma unroll
        for (int k = 0; k < 16; k++) {
            float ar[4], br[4];
            *(float4*)ar = *(const float4*)&As[buf][k][trow * 4];
            *(float4*)br = *(const float4*)&Bs[buf][k][tcol * 4];
#pragma unroll
            for (int i = 0; i < 4; i++)
#pragma unroll
                for (int j = 0; j < 4; j++) acc[i][j] += ar[i] * br[j];
        }
        if (s + 1 < 32) {
            __syncthreads();
#pragma unroll
            for (int j = 0; j < 4; j++) As[buf ^ 1][lkc + j][lrow] = ((const float*)&ra)[j];
            *(float4*)&Bs[buf ^ 1][bkr][bn4] = rb;
            __syncthreads();
        }
    }
#pragma unroll
    for (int i = 0; i < 4; i++) {
        float4 o;
        o.x = acc[i][0] * QK_SCALE; o.y = acc[i][1] * QK_SCALE;
        o.z = acc[i][2] * QK_SCALE; o.w = acc[i][3] * QK_SCALE;
        *(float4*)&g_qt[(size_t)grow(m0 + trow * 4 + i) * DD + d0 + tcol * 4] = o;
    }
}

// ---------------------------------------------------------------------------
// fp16 HMMA norm GEMM: CTA 128(s)x128(e), loops 4 etiles internally (64 iters).
// 4-slot cp.async pipeline (82KB -> 2 CTAs/SM), no atomics, direct sumsq write.
// grid 1024 = b(64) x n(4) x stile(4), 256 thr (8 warps 4Mx2N, warp 32x64).
// ---------------------------------------------------------------------------
#define KN_ROWB   80
#define KN_ATILE  (128 * KN_ROWB)            // 10240
#define KN_STAGE  (2 * KN_ATILE)             // 20480
#define KN_SMEM   (4 * KN_STAGE)             // 81920
#define KN_ITERS  64                         // 4 etiles x 16 kstages

__global__ void __launch_bounds__(256) k_knorm_fp16() {
    extern __shared__ __align__(16) char smem[];
    uint32_t sbase = smem_u32(smem);

    int tid = threadIdx.x;
    int wid = tid >> 5, lane = tid & 31;
    int warp_m = wid & 3;
    int warp_n = wid >> 2;

    int bx = blockIdx.x;
    int stile = bx & 3;
    int n = (bx >> 2) & 3;
    int b = bx >> 4;
    int s0 = stile * 128;

    const __half* Abase = g_hH + (size_t)b * SS * DD;
    const __half* Bbase = g_wH + (size_t)n * DD * DD;

    int lrow = tid >> 1;
    int lhalf = tid & 1;
    size_t a_goff = (size_t)(s0 + lrow) * DD + lhalf * 16;
    uint32_t s_loff = (uint32_t)(lrow * KN_ROWB + lhalf * 32);

    int g = lane >> 3, lr = lane & 7;
    int a_row16 = ((g & 1) << 3) + lr;
    int a_kc = g >> 1;
    uint32_t a_off0 = (uint32_t)((warp_m * 32 + a_row16) * KN_ROWB + a_kc * 16);
    uint32_t a_off1 = a_off0 + 16 * KN_ROWB;
    int b_row16 = ((g >> 1) << 3) + lr;
    int b_kc = g & 1;
    uint32_t b_off[4];
#pragma unroll
    for (int p = 0; p < 4; p++)
        b_off[p] = (uint32_t)(KN_ATILE +
                   (warp_n * 64 + p * 16 + b_row16) * KN_ROWB + b_kc * 16);

    float acc[2][8][4];
#pragma unroll
    for (int mt = 0; mt < 2; mt++)
#pragma unroll
        for (int nt = 0; nt < 8; nt++)
#pragma unroll
            for (int c = 0; c < 4; c++) acc[mt][nt][c] = 0.0f;
    float rs[2][2] = {{0.f, 0.f}, {0.f, 0.f}};

    auto load_stage = [&](int j) {
        int et = j >> 4;
        int k0 = (j & 15) * 32;
        uint32_t sb = sbase + (uint32_t)(j & 3) * KN_STAGE;
        const __half* as = Abase + a_goff + k0;
        const __half* bs = Bbase + (size_t)(et * 128 + lrow) * DD + lhalf * 16 + k0;
        cp_async16(sb + s_loff, as);
        cp_async16(sb + s_loff + 16, as + 8);
        cp_async16(sb + KN_ATILE + s_loff, bs);
        cp_async16(sb + KN_ATILE + s_loff + 16, bs + 8);
        CPASYNC_COMMIT();
    };

    load_stage(0);
    load_stage(1);
    load_stage(2);

    for (int i = 0; i < KN_ITERS; i++) {
        if (i < KN_ITERS - 2)      { CPASYNC_WAIT2(); }
        else if (i == KN_ITERS - 2){ CPASYNC_WAIT1(); }
        else                       { CPASYNC_WAIT0(); }
        __syncthreads();
        if (i + 3 < KN_ITERS) load_stage(i + 3);

        uint32_t sb = sbase + (uint32_t)(i & 3) * KN_STAGE;
#pragma unroll
        for (int ks = 0; ks < 2; ks++) {
            uint32_t koff = (uint32_t)(ks * 32);
            uint32_t afrag[2][4];
            uint32_t bfrag[8][2];
            ldmatrix_x4(afrag[0][0], afrag[0][1], afrag[0][2], afrag[0][3],
                        sb + a_off0 + koff);
            ldmatrix_x4(afrag[1][0], afrag[1][1], afrag[1][2], afrag[1][3],
                        sb + a_off1 + koff);
#pragma unroll
            for (int p = 0; p < 4; p++) {
                ldmatrix_x4(bfrag[2 * p][0], bfrag[2 * p][1],
                            bfrag[2 * p + 1][0], bfrag[2 * p + 1][1],
                            sb + b_off[p] + koff);
            }
#pragma unroll
            for (int mt = 0; mt < 2; mt++)
#pragma unroll
                for (int nt = 0; nt < 8; nt++)
                    mma_fp16(acc[mt][nt], afrag[mt], bfrag[nt]);
        }

        if ((i & 15) == 15) {    // etile done: fold squares, reset acc
#pragma unroll
            for (int mt = 0; mt < 2; mt++) {
#pragma unroll
                for (int nt = 0; nt < 8; nt++) {
                    rs[mt][0] += acc[mt][nt][0] * acc[mt][nt][0]
                               + acc[mt][nt][1] * acc[mt][nt][1];
                    rs[mt][1] += acc[mt][nt][2] * acc[mt][nt][2]
                               + acc[mt][nt][3] * acc[mt][nt][3];
                    acc[mt][nt][0] = acc[mt][nt][1] = 0.f;
                    acc[mt][nt][2] = acc[mt][nt][3] = 0.f;
                }
            }
        }
    }

    // epilogue: quad-reduce, combine the 2 N-warps via smem, direct store
#pragma unroll
    for (int mt = 0; mt < 2; mt++) {
#pragma unroll
        for (int h = 0; h < 2; h++) {
            rs[mt][h] += __shfl_xor_sync(0xFFFFFFFFu, rs[mt][h], 1);
            rs[mt][h] += __shfl_xor_sync(0xFFFFFFFFu, rs[mt][h], 2);
        }
    }
    __syncthreads();
    float* ssum = (float*)smem;
    if (tid < 128) ssum[tid] = 0.0f;
    __syncthreads();
    if ((lane & 3) == 0) {
        int rbase = warp_m * 32 + (lane >> 2);
#pragma unroll
        for (int mt = 0; mt < 2; mt++) {
            atomicAdd(&ssum[rbase + mt * 16], rs[mt][0]);
            atomicAdd(&ssum[rbase + mt * 16 + 8], rs[mt][1]);
        }
    }
    __syncthreads();
    if (tid < 128)
        g_sumsq[((size_t)(b * NKVH + n)) * SS + s0 + tid] = ssum[tid];
}

// ---------------------------------------------------------------------------
// Scores: grid 256 = b(64) x stile(4), 256 thr (8 warps x 16 rows).
// g_sc[b][t][s] = masked, rms-scaled score.
// ---------------------------------------------------------------------------
__global__ void __launch_bounds__(256) k_scores(const float* __restrict__ hist,
                                                const void*  __restrict__ mask) {
    int b = blockIdx.x >> 2;
    int s0 = (blockIdx.x & 3) * 128;
    int tid = threadIdx.x;
    int wid = tid >> 5, lane = tid & 31;
    int mode = g_mask_mode;

    __shared__ float sqt[TT][DD];
    for (int i = tid; i < TT * DD; i += 256)
        sqt[i >> 9][i & 511] = g_qt[(size_t)(b * TT) * DD + i];
    __syncthreads();

    for (int r = 0; r < 16; r++) {
        int s = s0 + wid * 16 + r;
        const float4* hp = (const float4*)(hist + ((size_t)(b * SS + s)) * DD);
        float4 h[4];
#pragma unroll
        for (int i = 0; i < 4; i++) h[i] = hp[lane + 32 * i];
        float p[TT];
#pragma unroll
        for (int t = 0; t < TT; t++) {
            const float4* q4 = (const float4*)sqt[t];
            float a = 0.0f;
#pragma unroll
            for (int i = 0; i < 4; i++) {
                float4 q = q4[lane + 32 * i];
                a += q.x * h[i].x + q.y * h[i].y + q.z * h[i].z + q.w * h[i].w;
            }
            p[t] = a;
        }
#pragma unroll
        for (int off = 16; off > 0; off >>= 1)
#pragma unroll
            for (int t = 0; t < TT; t++)
                p[t] += __shfl_xor_sync(0xFFFFFFFFu, p[t], off);
        if (lane == 0) {
            bool mk = is_masked(mask, b * SS + s, mode);
#pragma unroll
            for (int t = 0; t < TT; t++) {
                int n = t >> 1;
                float inv = rsqrtf(g_sumsq[((size_t)(b * NKVH + n)) * SS + s]
                                   * (1.0f / (float)DD) + EPS);
                g_sc[((size_t)(b * TT + t)) * SS + s] = mk ? -INFINITY : p[t] * inv;
            }
        }
    }
}

// ---------------------------------------------------------------------------
// Softmax: grid 64 (b), 256 thr, warp per t row. Writes attn to out + g_sc.
// ---------------------------------------------------------------------------
__global__ void __launch_bounds__(256) k_softmax(float* __restrict__ out) {
    int b = blockIdx.x;
    int t = threadIdx.x >> 5, lane = threadIdx.x & 31;
    float* row = g_sc + ((size_t)(b * TT + t)) * SS;
    float v[16];
    float mx = -INFINITY;
#pragma unroll
    for (int j = 0; j < 16; j++) {
        v[j] = row[lane + 32 * j];
        mx = fmaxf(mx, v[j]);
    }
#pragma unroll
    for (int off = 16; off > 0; off >>= 1)
        mx = fmaxf(mx, __shfl_xor_sync(0xFFFFFFFFu, mx, off));
    float sum = 0.0f;
#pragma unroll
    for (int j = 0; j < 16; j++) { v[j] = expf(v[j] - mx); sum += v[j]; }
#pragma unroll
    for (int off = 16; off > 0; off >>= 1)
        sum += __shfl_xor_sync(0xFFFFFFFFu, sum, off);
    float is = 1.0f / sum;
    size_t wbase = (size_t)BB * TT * DD + ((size_t)(b * TT + t)) * SS;
#pragma unroll
    for (int j = 0; j < 16; j++) {
        float a = v[j] * is;
        row[lane + 32 * j] = a;
        out[wbase + lane + 32 * j] = a;
    }
}

// ---------------------------------------------------------------------------
// ctx partials: grid 256 = b(64) x stile(4), 512 thr (thread = d).
// g_ctxp[stile][b*TT+t][d] = sum_{s in stile} attn[t][s] * hist[b,s,d]
// ---------------------------------------------------------------------------
__global__ void __launch_bounds__(512) k_ctx(const float* __restrict__ hist) {
    int b = blockIdx.x >> 2;
    int stile = blockIdx.x & 3;
    int s0 = stile * 128;
    int tid = threadIdx.x;

    __shared__ float sat[TT][128];
    for (int i = tid; i < TT * 128; i += 512)
        sat[i >> 7][i & 127] = g_sc[((size_t)(b * TT + (i >> 7))) * SS + s0 + (i & 127)];
    __syncthreads();

    int d = tid;
    float acc[TT];
#pragma unroll
    for (int t = 0; t < TT; t++) acc[t] = 0.0f;
    const float* hp = hist + ((size_t)(b * SS + s0)) * DD + d;
    for (int s = 0; s < 128; s += 4) {
        float h0 = hp[(size_t)s * DD];
        float h1 = hp[(size_t)(s + 1) * DD];
        float h2 = hp[(size_t)(s + 2) * DD];
        float h3 = hp[(size_t)(s + 3) * DD];
#pragma unroll
        for (int t = 0; t < TT; t++) {
            float4 a = *(const float4*)&sat[t][s];
            acc[t] += a.x * h0 + a.y * h1 + a.z * h2 + a.w * h3;
        }
    }
#pragma unroll
    for (int t = 0; t < TT; t++)
        g_ctxp[stile][((size_t)(b * TT + t)) * DD + d] = acc[t];
}

// ---------------------------------------------------------------------------
// Out projection: tokens[m,e] = (sum of 4 ctx partials)[m,:] . Wv_n[e,:]
// grid 64 = n(4) x et(16); tile 128(M) x 32(N), 256 threads.
// ---------------------------------------------------------------------------
__global__ void __launch_bounds__(256) k_out(const float* __restrict__ Wv,
                                             float* __restrict__ out) {
    __shared__ float As[2][16][132];
    __shared__ float Bs[2][16][36];
    int tid = threadIdx.x;
    int n  = blockIdx.x >> 4;
    int e0 = (blockIdx.x & 15) * 32;

    int trow = tid >> 3;
    int tcol = tid & 7;

    float acc[4][4];
#pragma unroll
    for (int i = 0; i < 4; i++)
#pragma unroll
        for (int j = 0; j < 4; j++) acc[i][j] = 0.0f;

    int arow0 = tid >> 2, akc = (tid & 3) * 4;
    int brow = tid >> 2, bkc = (tid & 3) * 4;
    auto ctxrow = [&](int m) { return (m >> 1) * TT + n * 2 + (m & 1); };

    auto loadA = [&](int row, int off) {
        float4 r = *(const float4*)(&g_ctxp[0][0] + (size_t)row * DD + off);
#pragma unroll
        for (int p = 1; p < 4; p++) {
            float4 q = *(const float4*)(&g_ctxp[p][0] + (size_t)row * DD + off);
            r.x += q.x; r.y += q.y; r.z += q.z; r.w += q.w;
        }
        return r;
    };
    auto gload = [&](int s, float4* ra, float4* rb) {
        int k0 = s * 16;
        ra[0] = loadA(ctxrow(arow0), k0 + akc);
        ra[1] = loadA(ctxrow(arow0 + 64), k0 + akc);
        if (tid < 128)
            rb[0] = *(const float4*)(Wv + (size_t)(n * DD + e0 + brow) * DD + k0 + bkc);
    };
    auto sstore = [&](int buf, const float4* ra, const float4* rb) {
#pragma unroll
        for (int j = 0; j < 4; j++) {
            As[buf][akc + j][arow0]      = ((const float*)&ra[0])[j];
            As[buf][akc + j][arow0 + 64] = ((const float*)&ra[1])[j];
        }
        if (tid < 128)
#pragma unroll
            for (int j = 0; j < 4; j++)
                Bs[buf][bkc + j][brow] = ((const float*)&rb[0])[j];
    };

    float4 ra[2], rb[1];
    gload(0, ra, rb);
    sstore(0, ra, rb);
    __syncthreads();

    for (int s = 0; s < 32; s++) {
        int buf = s & 1;
        if (s + 1 < 32) gload(s + 1, ra, rb);
#pragma unroll
        for (int k = 0; k < 16; k++) {
            float arr[4], brr[4];
            *(float4*)arr = *(const float4*)&As[buf][k][trow * 4];
            *(float4*)brr = *(const float4*)&Bs[buf][k][tcol * 4];
#pragma unroll
            for (int i = 0; i < 4; i++)
#pragma unroll
                for (int j = 0; j < 4; j++) acc[i][j] += arr[i] * brr[j];
        }
        if (s + 1 < 32) {
            __syncthreads();
            sstore(buf ^ 1, ra, rb);
            __syncthreads();
        }
    }
#pragma unroll
    for (int i = 0; i < 4; i++) {
        int m = trow * 4 + i;
        *(float4*)&out[(size_t)ctxrow(m) * DD + e0 + tcol * 4] = *(float4*)acc[i];
    }
}

// ---------------------------------------------------------------------------
extern "C" void kernel_launch(void* const* d_in, const int* in_sizes, int n_in,
                              void* d_out, int out_size) {
    (void)in_sizes; (void)n_in; (void)out_size;
    const float* target = (const float*)d_in[0];
    const float* hist   = (const float*)d_in[1];
    const void*  mask   = d_in[2];
    const float* Wq     = (const float*)d_in[3];
    const float* Wk     = (const float*)d_in[4];
    const float* Wv     = (const float*)d_in[5];
    const float* qw     = (const float*)d_in[6];
    const float* kw     = (const float*)d_in[7];
    float* out = (float*)d_out;

    cudaFuncSetAttribute(k_knorm_fp16, cudaFuncAttributeMaxDynamicSharedMemorySize,
                         KN_SMEM);

    __half *hH, *wH;
    cudaGetSymbolAddress((void**)&hH, g_hH);
    cudaGetSymbolAddress((void**)&wH, g_wH);

    k_detect_mask<<<1, 256>>>((const unsigned int*)mask);
    k_tofp16<<<2048, 256>>>(hist, hH, BB * SS * DD / 4);
    k_tofp16<<<512, 256>>>(Wk, wH, NKVH * DD * DD / 4);
    k_qproj_gemm<<<64, 256>>>(target, Wq);
    k_qnorm<<<64, 256>>>(qw, kw);
    k_qtilde_gemm<<<64, 256>>>(Wk);
    k_knorm_fp16<<<BB * NKVH * 4, 256, KN_SMEM>>>();
    k_scores<<<256, 256>>>(hist, mask);
    k_softmax<<<64, 256>>>(out);
    k_ctx<<<256, 512>>>(hist);
    k_out<<<64, 256>>>(Wv, out);
}